// round 2
// baseline (speedup 1.0000x reference)
#include <cuda_runtime.h>
#include <math.h>

#define HIDDEN 2048
#define KVSIZE 512
#define BATCH  2
#define SEQ    2048
#define MTOT   (BATCH*SEQ)
#define NHEADS 32
#define HDIM   64

// ---------------- scratch (device globals; no allocations allowed) -----------
__device__ float g_q[(size_t)MTOT * HIDDEN];   // 33.5 MB
__device__ float g_k[(size_t)MTOT * KVSIZE];   //  8.4 MB
__device__ float g_v[(size_t)MTOT * KVSIZE];   //  8.4 MB
__device__ float g_o[(size_t)MTOT * HIDDEN];   // 33.5 MB

// ---------------- SGEMM + bias: C[M,N] = A[M,K] @ B[K,N] + bias --------------
#define BM 128
#define BN 128
#define BKK 16

__global__ __launch_bounds__(256, 2) void sgemm_bias(
    const float* __restrict__ A, const float* __restrict__ B,
    const float* __restrict__ bias, float* __restrict__ C,
    int M, int N, int K)
{
    __shared__ float As[BKK][BM];
    __shared__ float Bs[BKK][BN];

    const int tid  = threadIdx.x;
    const int brow = blockIdx.y;
    const int bcol = blockIdx.x;

    const float* Ab = A + (size_t)brow * BM * K;
    const float* Bb = B + (size_t)bcol * BN;

    const int arow  = tid >> 2;            // 0..63
    const int acol  = (tid & 3) * 4;       // 0,4,8,12
    const int brl   = tid >> 5;            // 0..7
    const int bcl   = (tid & 31) * 4;      // 0..124

    const int tr = (tid >> 4) * 8;         // 0..120
    const int tc = (tid & 15) * 8;         // 0..120

    float acc[8][8];
#pragma unroll
    for (int i = 0; i < 8; i++)
#pragma unroll
        for (int j = 0; j < 8; j++) acc[i][j] = 0.f;

    for (int k0 = 0; k0 < K; k0 += BKK) {
#pragma unroll
        for (int r = 0; r < 2; r++) {
            float4 v = *(const float4*)(Ab + (size_t)(arow + 64 * r) * K + k0 + acol);
            As[acol + 0][arow + 64 * r] = v.x;
            As[acol + 1][arow + 64 * r] = v.y;
            As[acol + 2][arow + 64 * r] = v.z;
            As[acol + 3][arow + 64 * r] = v.w;
        }
#pragma unroll
        for (int r = 0; r < 2; r++) {
            float4 v = *(const float4*)(Bb + (size_t)(k0 + brl + 8 * r) * N + bcl);
            *(float4*)(&Bs[brl + 8 * r][bcl]) = v;
        }
        __syncthreads();

#pragma unroll
        for (int kk = 0; kk < BKK; kk++) {
            float ra[8], rb[8];
            *(float4*)(ra)     = *(const float4*)(&As[kk][tr]);
            *(float4*)(ra + 4) = *(const float4*)(&As[kk][tr + 4]);
            *(float4*)(rb)     = *(const float4*)(&Bs[kk][tc]);
            *(float4*)(rb + 4) = *(const float4*)(&Bs[kk][tc + 4]);
#pragma unroll
            for (int i = 0; i < 8; i++)
#pragma unroll
                for (int j = 0; j < 8; j++)
                    acc[i][j] = fmaf(ra[i], rb[j], acc[i][j]);
        }
        __syncthreads();
    }

    float bb[8];
#pragma unroll
    for (int j = 0; j < 8; j++) bb[j] = bias[bcol * BN + tc + j];

#pragma unroll
    for (int i = 0; i < 8; i++) {
        float* Crow = C + (size_t)(brow * BM + tr + i) * N + bcol * BN + tc;
        float4 v0, v1;
        v0.x = acc[i][0] + bb[0]; v0.y = acc[i][1] + bb[1];
        v0.z = acc[i][2] + bb[2]; v0.w = acc[i][3] + bb[3];
        v1.x = acc[i][4] + bb[4]; v1.y = acc[i][5] + bb[5];
        v1.z = acc[i][6] + bb[6]; v1.w = acc[i][7] + bb[7];
        *(float4*)(Crow)     = v0;
        *(float4*)(Crow + 4) = v1;
    }
}

// ---------------- Flash attention: one (64-query-rows, head) tile per CTA ----
// grid: (SEQ/64, 32 heads, BATCH), 256 threads
// shared: Qs[64][68] + Ks[64][68] + Vs[64][68]; P reuses Ks buffer.
#define APAD 68
#define ATTN_SMEM (3 * 64 * APAD * (int)sizeof(float))

__global__ __launch_bounds__(256, 4) void attn_kernel(
    const float* __restrict__ q, const float* __restrict__ k,
    const float* __restrict__ v, const float* __restrict__ mask,
    float* __restrict__ o)
{
    extern __shared__ float sm[];
    float (*Qs)[APAD] = (float (*)[APAD])sm;
    float (*Ks)[APAD] = (float (*)[APAD])(sm + 64 * APAD);
    float (*Vs)[APAD] = (float (*)[APAD])(sm + 2 * 64 * APAD);
    float (*Ps)[APAD] = Ks;   // reuse after S is computed

    const int tid  = threadIdx.x;
    const int qb   = blockIdx.x;
    const int head = blockIdx.y;
    const int b    = blockIdx.z;
    const int kh   = head >> 2;
    const int r0   = qb * 64;

    const float* qbase = q + ((size_t)b * SEQ + r0) * HIDDEN + head * HDIM;
    const float* kbase = k + (size_t)b * SEQ * KVSIZE + kh * HDIM;
    const float* vbase = v + (size_t)b * SEQ * KVSIZE + kh * HDIM;
    const float* mbase = mask + (size_t)b * SEQ;

    // load Q tile: 64 rows x 64 cols
    {
        const int row = tid >> 2;
        const int c0  = (tid & 3) * 16;
        const float* src = qbase + (size_t)row * HIDDEN + c0;
#pragma unroll
        for (int c = 0; c < 4; c++)
            *(float4*)(&Qs[row][c0 + c * 4]) = *(const float4*)(src + c * 4);
    }

    const int ty = tid >> 4;   // 0..15 -> rows ty*4..ty*4+3
    const int tx = tid & 15;   // 0..15 -> cols tx*4..tx*4+3

    float m_i[4], l_i[4], O[4][4];
#pragma unroll
    for (int i = 0; i < 4; i++) {
        m_i[i] = -1e30f; l_i[i] = 0.f;
#pragma unroll
        for (int j = 0; j < 4; j++) O[i][j] = 0.f;
    }
    const float scale = 0.125f;  // 1/sqrt(64)

    for (int t = 0; t < SEQ / 64; t++) {
        // load K,V tiles (64 x 64, row stride KVSIZE)
        {
            const int row = tid >> 2;
            const int c0  = (tid & 3) * 16;
            const float* ks = kbase + (size_t)(t * 64 + row) * KVSIZE + c0;
            const float* vs = vbase + (size_t)(t * 64 + row) * KVSIZE + c0;
#pragma unroll
            for (int c = 0; c < 4; c++) {
                *(float4*)(&Ks[row][c0 + c * 4]) = *(const float4*)(ks + c * 4);
                *(float4*)(&Vs[row][c0 + c * 4]) = *(const float4*)(vs + c * 4);
            }
        }
        __syncthreads();

        // S = Q @ K^T  (4x4 per thread)
        float sreg[4][4];
#pragma unroll
        for (int i = 0; i < 4; i++)
#pragma unroll
            for (int j = 0; j < 4; j++) sreg[i][j] = 0.f;

#pragma unroll 4
        for (int d = 0; d < HDIM; d += 4) {
            float4 qa[4], kb[4];
#pragma unroll
            for (int i = 0; i < 4; i++) qa[i] = *(const float4*)(&Qs[ty * 4 + i][d]);
#pragma unroll
            for (int j = 0; j < 4; j++) kb[j] = *(const float4*)(&Ks[tx * 4 + j][d]);
#pragma unroll
            for (int i = 0; i < 4; i++)
#pragma unroll
                for (int j = 0; j < 4; j++) {
                    sreg[i][j] = fmaf(qa[i].x, kb[j].x, sreg[i][j]);
                    sreg[i][j] = fmaf(qa[i].y, kb[j].y, sreg[i][j]);
                    sreg[i][j] = fmaf(qa[i].z, kb[j].z, sreg[i][j]);
                    sreg[i][j] = fmaf(qa[i].w, kb[j].w, sreg[i][j]);
                }
        }

        float mj[4];
#pragma unroll
        for (int j = 0; j < 4; j++) mj[j] = mbase[t * 64 + tx * 4 + j];

        float alpha[4];
#pragma unroll
        for (int i = 0; i < 4; i++) {
            float rmax = -1e30f;
#pragma unroll
            for (int j = 0; j < 4; j++) {
                sreg[i][j] = sreg[i][j] * scale + mj[j];
                rmax = fmaxf(rmax, sreg[i][j]);
            }
#pragma unroll
            for (int off = 8; off >= 1; off >>= 1)
                rmax = fmaxf(rmax, __shfl_xor_sync(0xffffffffu, rmax, off, 16));
            float mnew = fmaxf(m_i[i], rmax);
            alpha[i] = __expf(m_i[i] - mnew);
            m_i[i] = mnew;
            float rsum = 0.f;
#pragma unroll
            for (int j = 0; j < 4; j++) {
                float p = __expf(sreg[i][j] - mnew);
                sreg[i][j] = p;
                rsum += p;
            }
#pragma unroll
            for (int off = 8; off >= 1; off >>= 1)
                rsum += __shfl_xor_sync(0xffffffffu, rsum, off, 16);
            l_i[i] = l_i[i] * alpha[i] + rsum;
#pragma unroll
            for (int j = 0; j < 4; j++) O[i][j] *= alpha[i];
        }

        __syncthreads();   // everyone done reading Ks
#pragma unroll
        for (int i = 0; i < 4; i++)
#pragma unroll
            for (int j = 0; j < 4; j++)
                Ps[ty * 4 + i][tx * 4 + j] = sreg[i][j];
        __syncthreads();

        // O += P @ V
#pragma unroll 4
        for (int kk = 0; kk < 64; kk += 4) {
            float4 pv[4], vv[4];
#pragma unroll
            for (int i = 0; i < 4; i++) pv[i] = *(const float4*)(&Ps[ty * 4 + i][kk]);
#pragma unroll
            for (int c = 0; c < 4; c++) vv[c] = *(const float4*)(&Vs[kk + c][tx * 4]);
#pragma unroll
            for (int i = 0; i < 4; i++) {
                O[i][0] = fmaf(pv[i].x, vv[0].x, O[i][0]);
                O[i][0] = fmaf(pv[i].y, vv[1].x, O[i][0]);
                O[i][0] = fmaf(pv[i].z, vv[2].x, O[i][0]);
                O[i][0] = fmaf(pv[i].w, vv[3].x, O[i][0]);
                O[i][1] = fmaf(pv[i].x, vv[0].y, O[i][1]);
                O[i][1] = fmaf(pv[i].y, vv[1].y, O[i][1]);
                O[i][1] = fmaf(pv[i].z, vv[2].y, O[i][1]);
                O[i][1] = fmaf(pv[i].w, vv[3].y, O[i][1]);
                O[i][2] = fmaf(pv[i].x, vv[0].z, O[i][2]);
                O[i][2] = fmaf(pv[i].y, vv[1].z, O[i][2]);
                O[i][2] = fmaf(pv[i].z, vv[2].z, O[i][2]);
                O[i][2] = fmaf(pv[i].w, vv[3].z, O[i][2]);
                O[i][3] = fmaf(pv[i].x, vv[0].w, O[i][3]);
                O[i][3] = fmaf(pv[i].y, vv[1].w, O[i][3]);
                O[i][3] = fmaf(pv[i].z, vv[2].w, O[i][3]);
                O[i][3] = fmaf(pv[i].w, vv[3].w, O[i][3]);
            }
        }
        __syncthreads();   // before next tile overwrites Ks/Vs
    }

    // normalize + store
#pragma unroll
    for (int i = 0; i < 4; i++) {
        float inv = __frcp_rn(l_i[i]);
        float4 ov;
        ov.x = O[i][0] * inv; ov.y = O[i][1] * inv;
        ov.z = O[i][2] * inv; ov.w = O[i][3] * inv;
        float* dst = o + ((size_t)b * SEQ + r0 + ty * 4 + i) * HIDDEN + head * HDIM + tx * 4;
        *(float4*)dst = ov;
    }
}

// ---------------- host launcher ----------------------------------------------
extern "C" void kernel_launch(void* const* d_in, const int* in_sizes, int n_in,
                              void* d_out, int out_size)
{
    const float* x    = (const float*)d_in[0];
    const float* mask = (const float*)d_in[1];
    const float* Wq   = (const float*)d_in[2];
    const float* bq   = (const float*)d_in[3];
    const float* Wk   = (const float*)d_in[4];
    const float* bk   = (const float*)d_in[5];
    const float* Wv   = (const float*)d_in[6];
    const float* bv   = (const float*)d_in[7];
    const float* Wo   = (const float*)d_in[8];
    const float* bo   = (const float*)d_in[9];
    float* out = (float*)d_out;

    float *q, *k, *v, *o;
    cudaGetSymbolAddress((void**)&q, g_q);
    cudaGetSymbolAddress((void**)&k, g_k);
    cudaGetSymbolAddress((void**)&v, g_v);
    cudaGetSymbolAddress((void**)&o, g_o);

    cudaFuncSetAttribute(attn_kernel, cudaFuncAttributeMaxDynamicSharedMemorySize, ATTN_SMEM);

    dim3 blk(256);
    sgemm_bias<<<dim3(HIDDEN / BN, MTOT / BM), blk>>>(x, Wq, bq, q, MTOT, HIDDEN, HIDDEN);
    sgemm_bias<<<dim3(KVSIZE / BN, MTOT / BM), blk>>>(x, Wk, bk, k, MTOT, KVSIZE, HIDDEN);
    sgemm_bias<<<dim3(KVSIZE / BN, MTOT / BM), blk>>>(x, Wv, bv, v, MTOT, KVSIZE, HIDDEN);
    attn_kernel<<<dim3(SEQ / 64, NHEADS, BATCH), blk, ATTN_SMEM>>>(q, k, v, mask, o);
    sgemm_bias<<<dim3(HIDDEN / BN, MTOT / BM), blk>>>(o, Wo, bo, out, MTOT, HIDDEN, HIDDEN);
}

// round 5
// speedup vs baseline: 1.2988x; 1.2988x over previous
#include <cuda_runtime.h>
#include <cstdint>
#include <math.h>

#define HIDDEN 2048
#define KVSIZE 512
#define BATCH  2
#define SEQ    2048
#define MTOT   (BATCH*SEQ)
#define NHEADS 32
#define HDIM   64

// ---------------- scratch (device globals; no allocations allowed) -----------
__device__ float g_q[(size_t)MTOT * HIDDEN];
__device__ float g_k[(size_t)MTOT * KVSIZE];
__device__ float g_v[(size_t)MTOT * KVSIZE];
__device__ float g_o[(size_t)MTOT * HIDDEN];
__device__ float g_xr[(size_t)MTOT * HIDDEN];          // x rounded to tf32
__device__ float g_wqt[(size_t)HIDDEN * HIDDEN];       // W^T, rounded to tf32
__device__ float g_wkt[(size_t)KVSIZE * HIDDEN];
__device__ float g_wvt[(size_t)KVSIZE * HIDDEN];
__device__ float g_wot[(size_t)HIDDEN * HIDDEN];

// ---------------- helpers -----------------------------------------------------
__device__ __forceinline__ uint32_t smem_u32(const void* p) {
    uint32_t a;
    asm("{ .reg .u64 t; cvta.to.shared.u64 t, %1; cvt.u32.u64 %0, t; }" : "=r"(a) : "l"(p));
    return a;
}
__device__ __forceinline__ float f2tf32(float x) {
    float y;
    asm("cvt.rna.tf32.f32 %0, %1;" : "=f"(y) : "f"(x));
    return y;
}
__device__ __forceinline__ void cp_async16(uint32_t saddr, const void* g) {
    asm volatile("cp.async.cg.shared.global [%0], [%1], 16;" :: "r"(saddr), "l"(g));
}
__device__ __forceinline__ void cp_commit() { asm volatile("cp.async.commit_group;"); }
template<int N> __device__ __forceinline__ void cp_wait() {
    asm volatile("cp.async.wait_group %0;" :: "n"(N));
}
__device__ __forceinline__ void mma_tf32(float* c, const uint32_t* a, const uint32_t* b) {
    asm volatile(
        "mma.sync.aligned.m16n8k8.row.col.f32.tf32.tf32.f32 "
        "{%0,%1,%2,%3}, {%4,%5,%6,%7}, {%8,%9}, {%0,%1,%2,%3};"
        : "+f"(c[0]), "+f"(c[1]), "+f"(c[2]), "+f"(c[3])
        : "r"(a[0]), "r"(a[1]), "r"(a[2]), "r"(a[3]), "r"(b[0]), "r"(b[1]));
}

// ---------------- tf32 mma.sync GEMM: C[M,N] = A[M,K] @ Bt[N,K]^T + bias ------
// A, Bt K-major fp32 (pre-rounded to tf32). 128x128 tile, BK=32, double-buffer.
#define GBM 128
#define GBN 128
#define GBK 32
#define LDS_PAD 36                              // floats per smem row (144 B)
#define STAGE_F (128 * LDS_PAD)                 // floats per matrix per stage
#define GSMEM_BYTES (2 * 2 * STAGE_F * 4)       // 73728 B

__global__ __launch_bounds__(256) void gemm_tf32(
    const float* __restrict__ A, const float* __restrict__ Bt,
    const float* __restrict__ bias, float* __restrict__ C,
    int M, int N, int K)
{
    extern __shared__ float sm[];
    const uint32_t sbase = smem_u32(sm);
    const int tid  = threadIdx.x;
    const int wid  = tid >> 5, lane = tid & 31;
    const int m0   = blockIdx.y * GBM, n0 = blockIdx.x * GBN;
    const int wm   = (wid >> 2) * 64;           // warp row offset (0,64)
    const int wn   = (wid & 3) * 32;            // warp col offset (0..96)
    const int lr   = lane >> 2;                 // 0..7
    const int lc   = lane & 3;                  // 0..3

    // stage s: A at sbase + s*2*STAGE_F*4, B right after A
    auto stageA = [&](int s) { return sbase + (uint32_t)s * 2u * STAGE_F * 4u; };
    auto stageB = [&](int s) { return stageA(s) + STAGE_F * 4u; };

    const int ldr = tid >> 1;                    // 0..127 row to load
    const int ldc = (tid & 1) * 4;               // first 16B-chunk index (0 or 4)
    const float* garow = A  + (size_t)(m0 + ldr) * K;
    const float* gbrow = Bt + (size_t)(n0 + ldr) * K;

    auto load_stage = [&](int s, int t) {
        const uint32_t da = stageA(s) + (uint32_t)ldr * (LDS_PAD * 4);
        const uint32_t db = stageB(s) + (uint32_t)ldr * (LDS_PAD * 4);
        const float* ga = garow + t * GBK;
        const float* gb = gbrow + t * GBK;
#pragma unroll
        for (int i = 0; i < 4; i++) {
            const int ch = ldc + i;              // 0..7
            cp_async16(da + ch * 16, ga + ch * 4);
            cp_async16(db + ch * 16, gb + ch * 4);
        }
    };

    float acc[4][4][4];
#pragma unroll
    for (int mt = 0; mt < 4; mt++)
#pragma unroll
        for (int nt = 0; nt < 4; nt++)
#pragma unroll
            for (int i = 0; i < 4; i++) acc[mt][nt][i] = 0.f;

    const int T = K / GBK;
    load_stage(0, 0);
    cp_commit();

    for (int t = 0; t < T; t++) {
        const int s = t & 1;
        if (t + 1 < T) {
            load_stage(1 - s, t + 1);
            cp_commit();
            cp_wait<1>();
        } else {
            cp_wait<0>();
        }
        __syncthreads();

        const float* sa = sm + (size_t)s * 2 * STAGE_F;
        const float* sb = sa + STAGE_F;

#pragma unroll
        for (int k8 = 0; k8 < GBK / 8; k8++) {
            const int kb = k8 * 8;
            uint32_t af[4][4], bf[4][2];
#pragma unroll
            for (int mt = 0; mt < 4; mt++) {
                const float* ap = sa + (size_t)(wm + mt * 16 + lr) * LDS_PAD + kb + lc;
                af[mt][0] = __float_as_uint(ap[0]);
                af[mt][1] = __float_as_uint(ap[8 * LDS_PAD]);
                af[mt][2] = __float_as_uint(ap[4]);
                af[mt][3] = __float_as_uint(ap[8 * LDS_PAD + 4]);
            }
#pragma unroll
            for (int nt = 0; nt < 4; nt++) {
                const float* bp = sb + (size_t)(wn + nt * 8 + lr) * LDS_PAD + kb + lc;
                bf[nt][0] = __float_as_uint(bp[0]);
                bf[nt][1] = __float_as_uint(bp[4]);
            }
#pragma unroll
            for (int mt = 0; mt < 4; mt++)
#pragma unroll
                for (int nt = 0; nt < 4; nt++)
                    mma_tf32(acc[mt][nt], af[mt], bf[nt]);
        }
        __syncthreads();
    }

    // epilogue: fragment layout c0,c1 @ (lr, lc*2), c2,c3 @ (lr+8, lc*2)
#pragma unroll
    for (int nt = 0; nt < 4; nt++) {
        const int col = n0 + wn + nt * 8 + lc * 2;
        const float2 bb = *(const float2*)(bias + col);
#pragma unroll
        for (int mt = 0; mt < 4; mt++) {
            const int row = m0 + wm + mt * 16 + lr;
            float2 v0, v1;
            v0.x = acc[mt][nt][0] + bb.x; v0.y = acc[mt][nt][1] + bb.y;
            v1.x = acc[mt][nt][2] + bb.x; v1.y = acc[mt][nt][3] + bb.y;
            *(float2*)(C + (size_t)row * N + col)       = v0;
            *(float2*)(C + (size_t)(row + 8) * N + col) = v1;
        }
    }
}

// ---------------- transpose + tf32-round weights: Wt[n][k] = rnd(W[k][n]) -----
__global__ __launch_bounds__(256, 4) void transpose_rnd(
    const float* __restrict__ W, float* __restrict__ Wt, int K, int N)
{
    __shared__ float t[32][33];
    const int tx = threadIdx.x & 31, ty4 = (threadIdx.x >> 5) * 4;
    const int k0 = blockIdx.y * 32, n0 = blockIdx.x * 32;
#pragma unroll
    for (int r = 0; r < 4; r++)
        t[ty4 + r][tx] = W[(size_t)(k0 + ty4 + r) * N + n0 + tx];
    __syncthreads();
#pragma unroll
    for (int r = 0; r < 4; r++)
        Wt[(size_t)(n0 + ty4 + r) * K + k0 + tx] = f2tf32(t[tx][ty4 + r]);
}

// ---------------- elementwise tf32 rounding -----------------------------------
__global__ __launch_bounds__(256, 8) void round_tf32_vec(
    const float* __restrict__ in, float* __restrict__ out, size_t n4)
{
    size_t i = (size_t)blockIdx.x * blockDim.x + threadIdx.x;
    if (i < n4) {
        float4 v = ((const float4*)in)[i];
        v.x = f2tf32(v.x); v.y = f2tf32(v.y); v.z = f2tf32(v.z); v.w = f2tf32(v.w);
        ((float4*)out)[i] = v;
    }
}

// ---------------- Flash attention (SIMT fp32, unchanged core) -----------------
#define APAD 68
#define ATTN_SMEM (3 * 64 * APAD * (int)sizeof(float))

__global__ __launch_bounds__(256, 4) void attn_kernel(
    const float* __restrict__ q, const float* __restrict__ k,
    const float* __restrict__ v, const float* __restrict__ mask,
    float* __restrict__ o)
{
    extern __shared__ float sm[];
    float (*Qs)[APAD] = (float (*)[APAD])sm;
    float (*Ks)[APAD] = (float (*)[APAD])(sm + 64 * APAD);
    float (*Vs)[APAD] = (float (*)[APAD])(sm + 2 * 64 * APAD);
    float (*Ps)[APAD] = Ks;

    const int tid  = threadIdx.x;
    const int qb   = blockIdx.x;
    const int head = blockIdx.y;
    const int b    = blockIdx.z;
    const int kh   = head >> 2;
    const int r0   = qb * 64;

    const float* qbase = q + ((size_t)b * SEQ + r0) * HIDDEN + head * HDIM;
    const float* kbase = k + (size_t)b * SEQ * KVSIZE + kh * HDIM;
    const float* vbase = v + (size_t)b * SEQ * KVSIZE + kh * HDIM;
    const float* mbase = mask + (size_t)b * SEQ;

    {
        const int row = tid >> 2;
        const int c0  = (tid & 3) * 16;
        const float* src = qbase + (size_t)row * HIDDEN + c0;
#pragma unroll
        for (int c = 0; c < 4; c++)
            *(float4*)(&Qs[row][c0 + c * 4]) = *(const float4*)(src + c * 4);
    }

    const int ty = tid >> 4;
    const int tx = tid & 15;

    float m_i[4], l_i[4], O[4][4];
#pragma unroll
    for (int i = 0; i < 4; i++) {
        m_i[i] = -1e30f; l_i[i] = 0.f;
#pragma unroll
        for (int j = 0; j < 4; j++) O[i][j] = 0.f;
    }
    const float scale = 0.125f;

    for (int t = 0; t < SEQ / 64; t++) {
        {
            const int row = tid >> 2;
            const int c0  = (tid & 3) * 16;
            const float* ks = kbase + (size_t)(t * 64 + row) * KVSIZE + c0;
            const float* vs = vbase + (size_t)(t * 64 + row) * KVSIZE + c0;
#pragma unroll
            for (int c = 0; c < 4; c++) {
                *(float4*)(&Ks[row][c0 + c * 4]) = *(const float4*)(ks + c * 4);
                *(float4*)(&Vs[row][c0 + c * 4]) = *(const float4*)(vs + c * 4);
            }
        }
        __syncthreads();

        float sreg[4][4];
#pragma unroll
        for (int i = 0; i < 4; i++)
#pragma unroll
            for (int j = 0; j < 4; j++) sreg[i][j] = 0.f;

#pragma unroll 4
        for (int d = 0; d < HDIM; d += 4) {
            float4 qa[4], kb[4];
#pragma unroll
            for (int i = 0; i < 4; i++) qa[i] = *(const float4*)(&Qs[ty * 4 + i][d]);
#pragma unroll
            for (int j = 0; j < 4; j++) kb[j] = *(const float4*)(&Ks[tx * 4 + j][d]);
#pragma unroll
            for (int i = 0; i < 4; i++)
#pragma unroll
                for (int j = 0; j < 4; j++) {
                    sreg[i][j] = fmaf(qa[i].x, kb[j].x, sreg[i][j]);
                    sreg[i][j] = fmaf(qa[i].y, kb[j].y, sreg[i][j]);
                    sreg[i][j] = fmaf(qa[i].z, kb[j].z, sreg[i][j]);
                    sreg[i][j] = fmaf(qa[i].w, kb[j].w, sreg[i][j]);
                }
        }

        float mj[4];
#pragma unroll
        for (int j = 0; j < 4; j++) mj[j] = mbase[t * 64 + tx * 4 + j];

        float alpha[4];
#pragma unroll
        for (int i = 0; i < 4; i++) {
            float rmax = -1e30f;
#pragma unroll
            for (int j = 0; j < 4; j++) {
                sreg[i][j] = sreg[i][j] * scale + mj[j];
                rmax = fmaxf(rmax, sreg[i][j]);
            }
#pragma unroll
            for (int off = 8; off >= 1; off >>= 1)
                rmax = fmaxf(rmax, __shfl_xor_sync(0xffffffffu, rmax, off, 16));
            float mnew = fmaxf(m_i[i], rmax);
            alpha[i] = __expf(m_i[i] - mnew);
            m_i[i] = mnew;
            float rsum = 0.f;
#pragma unroll
            for (int j = 0; j < 4; j++) {
                float p = __expf(sreg[i][j] - mnew);
                sreg[i][j] = p;
                rsum += p;
            }
#pragma unroll
            for (int off = 8; off >= 1; off >>= 1)
                rsum += __shfl_xor_sync(0xffffffffu, rsum, off, 16);
            l_i[i] = l_i[i] * alpha[i] + rsum;
#pragma unroll
            for (int j = 0; j < 4; j++) O[i][j] *= alpha[i];
        }

        __syncthreads();
#pragma unroll
        for (int i = 0; i < 4; i++)
#pragma unroll
            for (int j = 0; j < 4; j++)
                Ps[ty * 4 + i][tx * 4 + j] = sreg[i][j];
        __syncthreads();

#pragma unroll 4
        for (int kk = 0; kk < 64; kk += 4) {
            float4 pv[4], vv[4];
#pragma unroll
            for (int i = 0; i < 4; i++) pv[i] = *(const float4*)(&Ps[ty * 4 + i][kk]);
#pragma unroll
            for (int c = 0; c < 4; c++) vv[c] = *(const float4*)(&Vs[kk + c][tx * 4]);
#pragma unroll
            for (int i = 0; i < 4; i++) {
                O[i][0] = fmaf(pv[i].x, vv[0].x, O[i][0]);
                O[i][0] = fmaf(pv[i].y, vv[1].x, O[i][0]);
                O[i][0] = fmaf(pv[i].z, vv[2].x, O[i][0]);
                O[i][0] = fmaf(pv[i].w, vv[3].x, O[i][0]);
                O[i][1] = fmaf(pv[i].x, vv[0].y, O[i][1]);
                O[i][1] = fmaf(pv[i].y, vv[1].y, O[i][1]);
                O[i][1] = fmaf(pv[i].z, vv[2].y, O[i][1]);
                O[i][1] = fmaf(pv[i].w, vv[3].y, O[i][1]);
                O[i][2] = fmaf(pv[i].x, vv[0].z, O[i][2]);
                O[i][2] = fmaf(pv[i].y, vv[1].z, O[i][2]);
                O[i][2] = fmaf(pv[i].z, vv[2].z, O[i][2]);
                O[i][2] = fmaf(pv[i].w, vv[3].z, O[i][2]);
                O[i][3] = fmaf(pv[i].x, vv[0].w, O[i][3]);
                O[i][3] = fmaf(pv[i].y, vv[1].w, O[i][3]);
                O[i][3] = fmaf(pv[i].z, vv[2].w, O[i][3]);
                O[i][3] = fmaf(pv[i].w, vv[3].w, O[i][3]);
            }
        }
        __syncthreads();
    }

    // normalize + store (rounded to tf32: feeds the tf32 O-projection)
#pragma unroll
    for (int i = 0; i < 4; i++) {
        float inv = __frcp_rn(l_i[i]);
        float4 ov;
        ov.x = f2tf32(O[i][0] * inv); ov.y = f2tf32(O[i][1] * inv);
        ov.z = f2tf32(O[i][2] * inv); ov.w = f2tf32(O[i][3] * inv);
        float* dst = o + ((size_t)b * SEQ + r0 + ty * 4 + i) * HIDDEN + head * HDIM + tx * 4;
        *(float4*)dst = ov;
    }
}

// ---------------- host launcher -----------------------------------------------
extern "C" void kernel_launch(void* const* d_in, const int* in_sizes, int n_in,
                              void* d_out, int out_size)
{
    const float* x    = (const float*)d_in[0];
    const float* mask = (const float*)d_in[1];
    const float* Wq   = (const float*)d_in[2];
    const float* bq   = (const float*)d_in[3];
    const float* Wk   = (const float*)d_in[4];
    const float* bk   = (const float*)d_in[5];
    const float* Wv   = (const float*)d_in[6];
    const float* bv   = (const float*)d_in[7];
    const float* Wo   = (const float*)d_in[8];
    const float* bo   = (const float*)d_in[9];
    float* out = (float*)d_out;

    float *q, *k, *v, *o, *xr, *wqt, *wkt, *wvt, *wot;
    cudaGetSymbolAddress((void**)&q,   g_q);
    cudaGetSymbolAddress((void**)&k,   g_k);
    cudaGetSymbolAddress((void**)&v,   g_v);
    cudaGetSymbolAddress((void**)&o,   g_o);
    cudaGetSymbolAddress((void**)&xr,  g_xr);
    cudaGetSymbolAddress((void**)&wqt, g_wqt);
    cudaGetSymbolAddress((void**)&wkt, g_wkt);
    cudaGetSymbolAddress((void**)&wvt, g_wvt);
    cudaGetSymbolAddress((void**)&wot, g_wot);

    cudaFuncSetAttribute(attn_kernel, cudaFuncAttributeMaxDynamicSharedMemorySize, ATTN_SMEM);
    cudaFuncSetAttribute(gemm_tf32, cudaFuncAttributeMaxDynamicSharedMemorySize, GSMEM_BYTES);

    // prep: round x, transpose+round weights
    {
        size_t n4 = (size_t)MTOT * HIDDEN / 4;
        round_tf32_vec<<<(unsigned)((n4 + 255) / 256), 256>>>(x, xr, n4);
    }
    transpose_rnd<<<dim3(HIDDEN / 32, HIDDEN / 32), 256>>>(Wq, wqt, HIDDEN, HIDDEN);
    transpose_rnd<<<dim3(KVSIZE / 32, HIDDEN / 32), 256>>>(Wk, wkt, HIDDEN, KVSIZE);
    transpose_rnd<<<dim3(KVSIZE / 32, HIDDEN / 32), 256>>>(Wv, wvt, HIDDEN, KVSIZE);
    transpose_rnd<<<dim3(HIDDEN / 32, HIDDEN / 32), 256>>>(Wo, wot, HIDDEN, HIDDEN);

    // projections (mma.sync tf32 tensor cores)
    gemm_tf32<<<dim3(HIDDEN / GBN, MTOT / GBM), 256, GSMEM_BYTES>>>(xr, wqt, bq, q, MTOT, HIDDEN, HIDDEN);
    gemm_tf32<<<dim3(KVSIZE / GBN, MTOT / GBM), 256, GSMEM_BYTES>>>(xr, wkt, bk, k, MTOT, KVSIZE, HIDDEN);
    gemm_tf32<<<dim3(KVSIZE / GBN, MTOT / GBM), 256, GSMEM_BYTES>>>(xr, wvt, bv, v, MTOT, KVSIZE, HIDDEN);

    // attention (SIMT fp32)
    attn_kernel<<<dim3(SEQ / 64, NHEADS, BATCH), 256, ATTN_SMEM>>>(q, k, v, mask, o);

    // output projection (mma.sync tf32)
    gemm_tf32<<<dim3(HIDDEN / GBN, MTOT / GBM), 256, GSMEM_BYTES>>>(o, wot, bo, out, MTOT, HIDDEN, HIDDEN);
}

// round 6
// speedup vs baseline: 3.3821x; 2.6040x over previous
#include <cuda_runtime.h>
#include <cstdint>
#include <math.h>

#define HIDDEN 2048
#define KVSIZE 512
#define BATCH  2
#define SEQ    2048
#define MTOT   (BATCH*SEQ)
#define NHEADS 32
#define HDIM   64

// ---------------- scratch (device globals; no allocations allowed) -----------
__device__ float g_q[(size_t)MTOT * HIDDEN];
__device__ float g_k[(size_t)MTOT * KVSIZE];
__device__ float g_v[(size_t)MTOT * KVSIZE];
__device__ float g_o[(size_t)MTOT * HIDDEN];
__device__ float g_xr[(size_t)MTOT * HIDDEN];          // x rounded to tf32
__device__ float g_wqt[(size_t)HIDDEN * HIDDEN];       // W^T, rounded to tf32
__device__ float g_wkt[(size_t)KVSIZE * HIDDEN];
__device__ float g_wvt[(size_t)KVSIZE * HIDDEN];
__device__ float g_wot[(size_t)HIDDEN * HIDDEN];

// ---------------- helpers -----------------------------------------------------
__device__ __forceinline__ uint32_t smem_u32(const void* p) {
    uint32_t a;
    asm("{ .reg .u64 t; cvta.to.shared.u64 t, %1; cvt.u32.u64 %0, t; }" : "=r"(a) : "l"(p));
    return a;
}
__device__ __forceinline__ float f2tf32(float x) {
    float y;
    asm("cvt.rna.tf32.f32 %0, %1;" : "=f"(y) : "f"(x));
    return y;
}
__device__ __forceinline__ void cp_async16(uint32_t saddr, const void* g) {
    asm volatile("cp.async.cg.shared.global [%0], [%1], 16;" :: "r"(saddr), "l"(g));
}
__device__ __forceinline__ void cp_commit() { asm volatile("cp.async.commit_group;"); }
template<int N> __device__ __forceinline__ void cp_wait() {
    asm volatile("cp.async.wait_group %0;" :: "n"(N));
}
__device__ __forceinline__ void mma_tf32(float* c, const uint32_t* a, const uint32_t* b) {
    asm volatile(
        "mma.sync.aligned.m16n8k8.row.col.f32.tf32.tf32.f32 "
        "{%0,%1,%2,%3}, {%4,%5,%6,%7}, {%8,%9}, {%0,%1,%2,%3};"
        : "+f"(c[0]), "+f"(c[1]), "+f"(c[2]), "+f"(c[3])
        : "r"(a[0]), "r"(a[1]), "r"(a[2]), "r"(a[3]), "r"(b[0]), "r"(b[1]));
}

// ---------------- tf32 mma.sync GEMM: C[M,N] = A[M,K] @ Bt[N,K]^T + bias ------
#define GBM 128
#define GBN 128
#define GBK 32
#define LDS_PAD 36
#define STAGE_F (128 * LDS_PAD)
#define GSMEM_BYTES (2 * 2 * STAGE_F * 4)

__global__ __launch_bounds__(256) void gemm_tf32(
    const float* __restrict__ A, const float* __restrict__ Bt,
    const float* __restrict__ bias, float* __restrict__ C,
    int M, int N, int K, int round_out)
{
    extern __shared__ float sm[];
    const uint32_t sbase = smem_u32(sm);
    const int tid  = threadIdx.x;
    const int wid  = tid >> 5, lane = tid & 31;
    const int m0   = blockIdx.y * GBM, n0 = blockIdx.x * GBN;
    const int wm   = (wid >> 2) * 64;
    const int wn   = (wid & 3) * 32;
    const int lr   = lane >> 2;
    const int lc   = lane & 3;

    auto stageA = [&](int s) { return sbase + (uint32_t)s * 2u * STAGE_F * 4u; };
    auto stageB = [&](int s) { return stageA(s) + STAGE_F * 4u; };

    const int ldr = tid >> 1;
    const int ldc = (tid & 1) * 4;
    const float* garow = A  + (size_t)(m0 + ldr) * K;
    const float* gbrow = Bt + (size_t)(n0 + ldr) * K;

    auto load_stage = [&](int s, int t) {
        const uint32_t da = stageA(s) + (uint32_t)ldr * (LDS_PAD * 4);
        const uint32_t db = stageB(s) + (uint32_t)ldr * (LDS_PAD * 4);
        const float* ga = garow + t * GBK;
        const float* gb = gbrow + t * GBK;
#pragma unroll
        for (int i = 0; i < 4; i++) {
            const int ch = ldc + i;
            cp_async16(da + ch * 16, ga + ch * 4);
            cp_async16(db + ch * 16, gb + ch * 4);
        }
    };

    float acc[4][4][4];
#pragma unroll
    for (int mt = 0; mt < 4; mt++)
#pragma unroll
        for (int nt = 0; nt < 4; nt++)
#pragma unroll
            for (int i = 0; i < 4; i++) acc[mt][nt][i] = 0.f;

    const int T = K / GBK;
    load_stage(0, 0);
    cp_commit();

    for (int t = 0; t < T; t++) {
        const int s = t & 1;
        if (t + 1 < T) {
            load_stage(1 - s, t + 1);
            cp_commit();
            cp_wait<1>();
        } else {
            cp_wait<0>();
        }
        __syncthreads();

        const float* sa = sm + (size_t)s * 2 * STAGE_F;
        const float* sb = sa + STAGE_F;

#pragma unroll
        for (int k8 = 0; k8 < GBK / 8; k8++) {
            const int kb = k8 * 8;
            uint32_t af[4][4], bf[4][2];
#pragma unroll
            for (int mt = 0; mt < 4; mt++) {
                const float* ap = sa + (size_t)(wm + mt * 16 + lr) * LDS_PAD + kb + lc;
                af[mt][0] = __float_as_uint(ap[0]);
                af[mt][1] = __float_as_uint(ap[8 * LDS_PAD]);
                af[mt][2] = __float_as_uint(ap[4]);
                af[mt][3] = __float_as_uint(ap[8 * LDS_PAD + 4]);
            }
#pragma unroll
            for (int nt = 0; nt < 4; nt++) {
                const float* bp = sb + (size_t)(wn + nt * 8 + lr) * LDS_PAD + kb + lc;
                bf[nt][0] = __float_as_uint(bp[0]);
                bf[nt][1] = __float_as_uint(bp[4]);
            }
#pragma unroll
            for (int mt = 0; mt < 4; mt++)
#pragma unroll
                for (int nt = 0; nt < 4; nt++)
                    mma_tf32(acc[mt][nt], af[mt], bf[nt]);
        }
        __syncthreads();
    }

#pragma unroll
    for (int nt = 0; nt < 4; nt++) {
        const int col = n0 + wn + nt * 8 + lc * 2;
        const float2 bb = *(const float2*)(bias + col);
#pragma unroll
        for (int mt = 0; mt < 4; mt++) {
            const int row = m0 + wm + mt * 16 + lr;
            float2 v0, v1;
            v0.x = acc[mt][nt][0] + bb.x; v0.y = acc[mt][nt][1] + bb.y;
            v1.x = acc[mt][nt][2] + bb.x; v1.y = acc[mt][nt][3] + bb.y;
            if (round_out) {
                v0.x = f2tf32(v0.x); v0.y = f2tf32(v0.y);
                v1.x = f2tf32(v1.x); v1.y = f2tf32(v1.y);
            }
            *(float2*)(C + (size_t)row * N + col)       = v0;
            *(float2*)(C + (size_t)(row + 8) * N + col) = v1;
        }
    }
}

// ---------------- transpose + tf32-round weights ------------------------------
__global__ __launch_bounds__(256, 4) void transpose_rnd(
    const float* __restrict__ W, float* __restrict__ Wt, int K, int N)
{
    __shared__ float t[32][33];
    const int tx = threadIdx.x & 31, ty4 = (threadIdx.x >> 5) * 4;
    const int k0 = blockIdx.y * 32, n0 = blockIdx.x * 32;
#pragma unroll
    for (int r = 0; r < 4; r++)
        t[ty4 + r][tx] = W[(size_t)(k0 + ty4 + r) * N + n0 + tx];
    __syncthreads();
#pragma unroll
    for (int r = 0; r < 4; r++)
        Wt[(size_t)(n0 + ty4 + r) * K + k0 + tx] = f2tf32(t[tx][ty4 + r]);
}

__global__ __launch_bounds__(256, 8) void round_tf32_vec(
    const float* __restrict__ in, float* __restrict__ out, size_t n4)
{
    size_t i = (size_t)blockIdx.x * blockDim.x + threadIdx.x;
    if (i < n4) {
        float4 v = ((const float4*)in)[i];
        v.x = f2tf32(v.x); v.y = f2tf32(v.y); v.z = f2tf32(v.z); v.w = f2tf32(v.w);
        ((float4*)out)[i] = v;
    }
}

// ---------------- Flash attention on mma.sync tf32 ----------------------------
// CTA: 128 query rows x 1 head. 8 warps, warp w owns rows w*16..w*16+15.
// Key tiles of 64, double-buffered via cp.async.
#define APD 68
#define ATT_Q_F  (128 * APD)
#define ATT_KV_F (64 * APD)
#define ATT_SMEM ((ATT_Q_F + 4 * ATT_KV_F) * 4)   // 104448 B

__global__ __launch_bounds__(256, 2) void attn_mma(
    const float* __restrict__ q, const float* __restrict__ k,
    const float* __restrict__ v, const float* __restrict__ mask,
    float* __restrict__ o)
{
    extern __shared__ float sm[];
    const uint32_t sbase = smem_u32(sm);
    float* Qs = sm;

    const int tid  = threadIdx.x;
    const int wid  = tid >> 5, lane = tid & 31;
    const int lr   = lane >> 2, lc = lane & 3;
    const int wm   = wid * 16;

    const int qb   = blockIdx.x;
    const int head = blockIdx.y;
    const int b    = blockIdx.z;
    const int kh   = head >> 2;
    const int r0   = qb * 128;

    const float* qbase = q + ((size_t)b * SEQ + r0) * HIDDEN + head * HDIM;
    const float* kbase = k + (size_t)b * SEQ * KVSIZE + kh * HDIM;
    const float* vbase = v + (size_t)b * SEQ * KVSIZE + kh * HDIM;
    const float* mbase = mask + (size_t)b * SEQ;

    // ---- load Q tile (128x64) via cp.async ----
    {
        const int row = tid >> 1, c0 = (tid & 1) * 32;
        const uint32_t dst = sbase + ((uint32_t)row * APD + c0) * 4u;
        const float* src = qbase + (size_t)row * HIDDEN + c0;
#pragma unroll
        for (int i = 0; i < 8; i++)
            cp_async16(dst + i * 16, src + i * 4);
    }

    // KV stage addresses
    auto ksAddr = [&](int s) { return sbase + (ATT_Q_F + (uint32_t)s * 2u * ATT_KV_F) * 4u; };
    const int kvrow = tid >> 2;                // 0..63
    const int kvcb  = (tid & 3) * 16;          // col base in floats

    auto load_kv = [&](int s, int t) {
        const uint32_t dk = ksAddr(s) + ((uint32_t)kvrow * APD + kvcb) * 4u;
        const uint32_t dv = dk + ATT_KV_F * 4u;
        const float* gk = kbase + (size_t)(t * 64 + kvrow) * KVSIZE + kvcb;
        const float* gv = vbase + (size_t)(t * 64 + kvrow) * KVSIZE + kvcb;
#pragma unroll
        for (int i = 0; i < 4; i++) {
            cp_async16(dk + i * 16, gk + i * 4);
            cp_async16(dv + i * 16, gv + i * 4);
        }
    };

    load_kv(0, 0);
    cp_commit();

    float Oacc[8][4];
#pragma unroll
    for (int dn = 0; dn < 8; dn++)
#pragma unroll
        for (int i = 0; i < 4; i++) Oacc[dn][i] = 0.f;
    float m1 = -1e30f, m2 = -1e30f, l1 = 0.f, l2 = 0.f;
    const float scale = 0.125f;

    const int T = SEQ / 64;
    for (int t = 0; t < T; t++) {
        const int s = t & 1;
        if (t + 1 < T) {
            load_kv(1 - s, t + 1);
            cp_commit();
            cp_wait<1>();
        } else {
            cp_wait<0>();
        }
        __syncthreads();

        const float* Ks = sm + ATT_Q_F + (size_t)s * 2 * ATT_KV_F;
        const float* Vs = Ks + ATT_KV_F;

        // ---- S = Q @ K^T ----
        float Sacc[8][4];
#pragma unroll
        for (int nt = 0; nt < 8; nt++)
#pragma unroll
            for (int i = 0; i < 4; i++) Sacc[nt][i] = 0.f;

#pragma unroll
        for (int k8 = 0; k8 < 8; k8++) {
            const int kb = k8 * 8;
            uint32_t af[4];
            const float* qp = Qs + (size_t)(wm + lr) * APD + kb + lc;
            af[0] = __float_as_uint(qp[0]);
            af[1] = __float_as_uint(qp[8 * APD]);
            af[2] = __float_as_uint(qp[4]);
            af[3] = __float_as_uint(qp[8 * APD + 4]);
#pragma unroll
            for (int nt = 0; nt < 8; nt++) {
                const float* kp = Ks + (size_t)(nt * 8 + lr) * APD + kb + lc;
                uint32_t bf[2];
                bf[0] = __float_as_uint(kp[0]);
                bf[1] = __float_as_uint(kp[4]);
                mma_tf32(Sacc[nt], af, bf);
            }
        }

        // ---- online softmax on fragments ----
        float mx1 = -1e30f, mx2 = -1e30f;
#pragma unroll
        for (int nt = 0; nt < 8; nt++) {
            const float2 mv = *(const float2*)(mbase + t * 64 + nt * 8 + 2 * lc);
            Sacc[nt][0] = Sacc[nt][0] * scale + mv.x;
            Sacc[nt][1] = Sacc[nt][1] * scale + mv.y;
            Sacc[nt][2] = Sacc[nt][2] * scale + mv.x;
            Sacc[nt][3] = Sacc[nt][3] * scale + mv.y;
            mx1 = fmaxf(mx1, fmaxf(Sacc[nt][0], Sacc[nt][1]));
            mx2 = fmaxf(mx2, fmaxf(Sacc[nt][2], Sacc[nt][3]));
        }
        mx1 = fmaxf(mx1, __shfl_xor_sync(0xffffffffu, mx1, 1));
        mx1 = fmaxf(mx1, __shfl_xor_sync(0xffffffffu, mx1, 2));
        mx2 = fmaxf(mx2, __shfl_xor_sync(0xffffffffu, mx2, 1));
        mx2 = fmaxf(mx2, __shfl_xor_sync(0xffffffffu, mx2, 2));

        const float mn1 = fmaxf(m1, mx1), mn2 = fmaxf(m2, mx2);
        const float al1 = __expf(m1 - mn1), al2 = __expf(m2 - mn2);
        m1 = mn1; m2 = mn2;

        float sum1 = 0.f, sum2 = 0.f;
#pragma unroll
        for (int nt = 0; nt < 8; nt++) {
            Sacc[nt][0] = __expf(Sacc[nt][0] - mn1);
            Sacc[nt][1] = __expf(Sacc[nt][1] - mn1);
            Sacc[nt][2] = __expf(Sacc[nt][2] - mn2);
            Sacc[nt][3] = __expf(Sacc[nt][3] - mn2);
            sum1 += Sacc[nt][0] + Sacc[nt][1];
            sum2 += Sacc[nt][2] + Sacc[nt][3];
        }
        sum1 += __shfl_xor_sync(0xffffffffu, sum1, 1);
        sum1 += __shfl_xor_sync(0xffffffffu, sum1, 2);
        sum2 += __shfl_xor_sync(0xffffffffu, sum2, 1);
        sum2 += __shfl_xor_sync(0xffffffffu, sum2, 2);
        l1 = l1 * al1 + sum1;
        l2 = l2 * al2 + sum2;

#pragma unroll
        for (int dn = 0; dn < 8; dn++) {
            Oacc[dn][0] *= al1; Oacc[dn][1] *= al1;
            Oacc[dn][2] *= al2; Oacc[dn][3] *= al2;
        }

        // ---- O += P @ V : P frags from Sacc via quad shuffles ----
        const int src0 = (lane & 28) | (lc >> 1);
        const int src1 = src0 + 2;
        const bool odd = (lc & 1);
#pragma unroll
        for (int kk = 0; kk < 8; kk++) {
            float s0 = __shfl_sync(0xffffffffu, Sacc[kk][0], src0);
            float s1 = __shfl_sync(0xffffffffu, Sacc[kk][1], src0);
            float s2 = __shfl_sync(0xffffffffu, Sacc[kk][0], src1);
            float s3 = __shfl_sync(0xffffffffu, Sacc[kk][1], src1);
            float s4 = __shfl_sync(0xffffffffu, Sacc[kk][2], src0);
            float s5 = __shfl_sync(0xffffffffu, Sacc[kk][3], src0);
            float s6 = __shfl_sync(0xffffffffu, Sacc[kk][2], src1);
            float s7 = __shfl_sync(0xffffffffu, Sacc[kk][3], src1);
            uint32_t af[4];
            af[0] = __float_as_uint(f2tf32(odd ? s1 : s0));   // P[r1][kk*8+lc]
            af[1] = __float_as_uint(f2tf32(odd ? s5 : s4));   // P[r2][kk*8+lc]
            af[2] = __float_as_uint(f2tf32(odd ? s3 : s2));   // P[r1][kk*8+lc+4]
            af[3] = __float_as_uint(f2tf32(odd ? s7 : s6));   // P[r2][kk*8+lc+4]
#pragma unroll
            for (int dn = 0; dn < 8; dn++) {
                const float* vp = Vs + (size_t)(kk * 8 + lc) * APD + dn * 8 + lr;
                uint32_t bf[2];
                bf[0] = __float_as_uint(vp[0]);
                bf[1] = __float_as_uint(vp[4 * APD]);
                mma_tf32(Oacc[dn], af, bf);
            }
        }
        __syncthreads();
    }

    // ---- normalize + store ----
    const float inv1 = __frcp_rn(l1), inv2 = __frcp_rn(l2);
    const int row1 = r0 + wm + lr, row2 = row1 + 8;
    float* o1 = o + ((size_t)b * SEQ + row1) * HIDDEN + head * HDIM;
    float* o2 = o + ((size_t)b * SEQ + row2) * HIDDEN + head * HDIM;
#pragma unroll
    for (int dn = 0; dn < 8; dn++) {
        const int col = dn * 8 + 2 * lc;
        float2 v1, v2;
        v1.x = f2tf32(Oacc[dn][0] * inv1); v1.y = f2tf32(Oacc[dn][1] * inv1);
        v2.x = f2tf32(Oacc[dn][2] * inv2); v2.y = f2tf32(Oacc[dn][3] * inv2);
        *(float2*)(o1 + col) = v1;
        *(float2*)(o2 + col) = v2;
    }
}

// ---------------- host launcher -----------------------------------------------
extern "C" void kernel_launch(void* const* d_in, const int* in_sizes, int n_in,
                              void* d_out, int out_size)
{
    const float* x    = (const float*)d_in[0];
    const float* mask = (const float*)d_in[1];
    const float* Wq   = (const float*)d_in[2];
    const float* bq   = (const float*)d_in[3];
    const float* Wk   = (const float*)d_in[4];
    const float* bk   = (const float*)d_in[5];
    const float* Wv   = (const float*)d_in[6];
    const float* bv   = (const float*)d_in[7];
    const float* Wo   = (const float*)d_in[8];
    const float* bo   = (const float*)d_in[9];
    float* out = (float*)d_out;

    float *q, *k, *v, *o, *xr, *wqt, *wkt, *wvt, *wot;
    cudaGetSymbolAddress((void**)&q,   g_q);
    cudaGetSymbolAddress((void**)&k,   g_k);
    cudaGetSymbolAddress((void**)&v,   g_v);
    cudaGetSymbolAddress((void**)&o,   g_o);
    cudaGetSymbolAddress((void**)&xr,  g_xr);
    cudaGetSymbolAddress((void**)&wqt, g_wqt);
    cudaGetSymbolAddress((void**)&wkt, g_wkt);
    cudaGetSymbolAddress((void**)&wvt, g_wvt);
    cudaGetSymbolAddress((void**)&wot, g_wot);

    cudaFuncSetAttribute(gemm_tf32, cudaFuncAttributeMaxDynamicSharedMemorySize, GSMEM_BYTES);
    cudaFuncSetAttribute(attn_mma,  cudaFuncAttributeMaxDynamicSharedMemorySize, ATT_SMEM);

    // prep
    {
        size_t n4 = (size_t)MTOT * HIDDEN / 4;
        round_tf32_vec<<<(unsigned)((n4 + 255) / 256), 256>>>(x, xr, n4);
    }
    transpose_rnd<<<dim3(HIDDEN / 32, HIDDEN / 32), 256>>>(Wq, wqt, HIDDEN, HIDDEN);
    transpose_rnd<<<dim3(KVSIZE / 32, HIDDEN / 32), 256>>>(Wk, wkt, HIDDEN, KVSIZE);
    transpose_rnd<<<dim3(KVSIZE / 32, HIDDEN / 32), 256>>>(Wv, wvt, HIDDEN, KVSIZE);
    transpose_rnd<<<dim3(HIDDEN / 32, HIDDEN / 32), 256>>>(Wo, wot, HIDDEN, HIDDEN);

    // projections (round outputs to tf32: consumed by tf32 attention mmas)
    gemm_tf32<<<dim3(HIDDEN / GBN, MTOT / GBM), 256, GSMEM_BYTES>>>(xr, wqt, bq, q, MTOT, HIDDEN, HIDDEN, 1);
    gemm_tf32<<<dim3(KVSIZE / GBN, MTOT / GBM), 256, GSMEM_BYTES>>>(xr, wkt, bk, k, MTOT, KVSIZE, HIDDEN, 1);
    gemm_tf32<<<dim3(KVSIZE / GBN, MTOT / GBM), 256, GSMEM_BYTES>>>(xr, wvt, bv, v, MTOT, KVSIZE, HIDDEN, 1);

    // attention (mma.sync tf32 flash)
    attn_mma<<<dim3(SEQ / 128, NHEADS, BATCH), 256, ATT_SMEM>>>(q, k, v, mask, o);

    // output projection (full fp32 out)
    gemm_tf32<<<dim3(HIDDEN / GBN, MTOT / GBM), 256, GSMEM_BYTES>>>(o, wot, bo, out, MTOT, HIDDEN, HIDDEN, 0);
}

// round 7
// speedup vs baseline: 3.5560x; 1.0514x over previous
#include <cuda_runtime.h>
#include <cstdint>
#include <math.h>

#define HIDDEN 2048
#define KVSIZE 512
#define BATCH  2
#define SEQ    2048
#define MTOT   (BATCH*SEQ)
#define NHEADS 32
#define HDIM   64
#define QKVN   (HIDDEN + 2 * KVSIZE)    // 3072 fused projection width

// ---------------- scratch (device globals; no allocations allowed) -----------
__device__ float g_qkv[(size_t)MTOT * QKVN];       // fused q|k|v, 50 MB
__device__ float g_o[(size_t)MTOT * HIDDEN];
__device__ float g_xr[(size_t)MTOT * HIDDEN];      // x rounded to tf32
__device__ float g_wt[(size_t)QKVN * HIDDEN];      // [Wq^T; Wk^T; Wv^T] tf32
__device__ float g_wot[(size_t)HIDDEN * HIDDEN];   // Wo^T tf32
__device__ float g_bqkv[QKVN];                     // bq|bk|bv

// ---------------- helpers -----------------------------------------------------
__device__ __forceinline__ uint32_t smem_u32(const void* p) {
    uint32_t a;
    asm("{ .reg .u64 t; cvta.to.shared.u64 t, %1; cvt.u32.u64 %0, t; }" : "=r"(a) : "l"(p));
    return a;
}
__device__ __forceinline__ float f2tf32(float x) {
    float y;
    asm("cvt.rna.tf32.f32 %0, %1;" : "=f"(y) : "f"(x));
    return y;
}
__device__ __forceinline__ void cp_async16(uint32_t saddr, const void* g) {
    asm volatile("cp.async.cg.shared.global [%0], [%1], 16;" :: "r"(saddr), "l"(g));
}
__device__ __forceinline__ void cp_commit() { asm volatile("cp.async.commit_group;"); }
template<int N> __device__ __forceinline__ void cp_wait() {
    asm volatile("cp.async.wait_group %0;" :: "n"(N));
}
__device__ __forceinline__ void mma_tf32(float* c, const uint32_t* a, const uint32_t* b) {
    asm volatile(
        "mma.sync.aligned.m16n8k8.row.col.f32.tf32.tf32.f32 "
        "{%0,%1,%2,%3}, {%4,%5,%6,%7}, {%8,%9}, {%0,%1,%2,%3};"
        : "+f"(c[0]), "+f"(c[1]), "+f"(c[2]), "+f"(c[3])
        : "r"(a[0]), "r"(a[1]), "r"(a[2]), "r"(a[3]), "r"(b[0]), "r"(b[1]));
}

// ---------------- tf32 mma.sync GEMM: C[M,N] = A[M,K] @ Bt[N,K]^T + bias ------
#define GBM 128
#define GBN 128
#define GBK 32
#define LDS_PAD 36
#define STAGE_F (128 * LDS_PAD)
#define GSMEM_BYTES (2 * 2 * STAGE_F * 4)

__global__ __launch_bounds__(256) void gemm_tf32(
    const float* __restrict__ A, const float* __restrict__ Bt,
    const float* __restrict__ bias, float* __restrict__ C,
    int M, int N, int K, int round_out)
{
    extern __shared__ float sm[];
    const uint32_t sbase = smem_u32(sm);
    const int tid  = threadIdx.x;
    const int wid  = tid >> 5, lane = tid & 31;
    const int m0   = blockIdx.y * GBM, n0 = blockIdx.x * GBN;
    const int wm   = (wid >> 2) * 64;
    const int wn   = (wid & 3) * 32;
    const int lr   = lane >> 2;
    const int lc   = lane & 3;

    auto stageA = [&](int s) { return sbase + (uint32_t)s * 2u * STAGE_F * 4u; };
    auto stageB = [&](int s) { return stageA(s) + STAGE_F * 4u; };

    const int ldr = tid >> 1;
    const int ldc = (tid & 1) * 4;
    const float* garow = A  + (size_t)(m0 + ldr) * K;
    const float* gbrow = Bt + (size_t)(n0 + ldr) * K;

    auto load_stage = [&](int s, int t) {
        const uint32_t da = stageA(s) + (uint32_t)ldr * (LDS_PAD * 4);
        const uint32_t db = stageB(s) + (uint32_t)ldr * (LDS_PAD * 4);
        const float* ga = garow + t * GBK;
        const float* gb = gbrow + t * GBK;
#pragma unroll
        for (int i = 0; i < 4; i++) {
            const int ch = ldc + i;
            cp_async16(da + ch * 16, ga + ch * 4);
            cp_async16(db + ch * 16, gb + ch * 4);
        }
    };

    float acc[4][4][4];
#pragma unroll
    for (int mt = 0; mt < 4; mt++)
#pragma unroll
        for (int nt = 0; nt < 4; nt++)
#pragma unroll
            for (int i = 0; i < 4; i++) acc[mt][nt][i] = 0.f;

    const int T = K / GBK;
    load_stage(0, 0);
    cp_commit();

    for (int t = 0; t < T; t++) {
        const int s = t & 1;
        if (t + 1 < T) {
            load_stage(1 - s, t + 1);
            cp_commit();
            cp_wait<1>();
        } else {
            cp_wait<0>();
        }
        __syncthreads();

        const float* sa = sm + (size_t)s * 2 * STAGE_F;
        const float* sb = sa + STAGE_F;

#pragma unroll
        for (int k8 = 0; k8 < GBK / 8; k8++) {
            const int kb = k8 * 8;
            uint32_t af[4][4], bf[4][2];
#pragma unroll
            for (int mt = 0; mt < 4; mt++) {
                const float* ap = sa + (size_t)(wm + mt * 16 + lr) * LDS_PAD + kb + lc;
                af[mt][0] = __float_as_uint(ap[0]);
                af[mt][1] = __float_as_uint(ap[8 * LDS_PAD]);
                af[mt][2] = __float_as_uint(ap[4]);
                af[mt][3] = __float_as_uint(ap[8 * LDS_PAD + 4]);
            }
#pragma unroll
            for (int nt = 0; nt < 4; nt++) {
                const float* bp = sb + (size_t)(wn + nt * 8 + lr) * LDS_PAD + kb + lc;
                bf[nt][0] = __float_as_uint(bp[0]);
                bf[nt][1] = __float_as_uint(bp[4]);
            }
#pragma unroll
            for (int mt = 0; mt < 4; mt++)
#pragma unroll
                for (int nt = 0; nt < 4; nt++)
                    mma_tf32(acc[mt][nt], af[mt], bf[nt]);
        }
        __syncthreads();
    }

#pragma unroll
    for (int nt = 0; nt < 4; nt++) {
        const int col = n0 + wn + nt * 8 + lc * 2;
        const float2 bb = *(const float2*)(bias + col);
#pragma unroll
        for (int mt = 0; mt < 4; mt++) {
            const int row = m0 + wm + mt * 16 + lr;
            float2 v0, v1;
            v0.x = acc[mt][nt][0] + bb.x; v0.y = acc[mt][nt][1] + bb.y;
            v1.x = acc[mt][nt][2] + bb.x; v1.y = acc[mt][nt][3] + bb.y;
            if (round_out) {
                v0.x = f2tf32(v0.x); v0.y = f2tf32(v0.y);
                v1.x = f2tf32(v1.x); v1.y = f2tf32(v1.y);
            }
            *(float2*)(C + (size_t)row * N + col)       = v0;
            *(float2*)(C + (size_t)(row + 8) * N + col) = v1;
        }
    }
}

// ---------------- transpose + tf32-round weights ------------------------------
__global__ __launch_bounds__(256, 4) void transpose_rnd(
    const float* __restrict__ W, float* __restrict__ Wt, int K, int N)
{
    __shared__ float t[32][33];
    const int tx = threadIdx.x & 31, ty4 = (threadIdx.x >> 5) * 4;
    const int k0 = blockIdx.y * 32, n0 = blockIdx.x * 32;
#pragma unroll
    for (int r = 0; r < 4; r++)
        t[ty4 + r][tx] = W[(size_t)(k0 + ty4 + r) * N + n0 + tx];
    __syncthreads();
#pragma unroll
    for (int r = 0; r < 4; r++)
        Wt[(size_t)(n0 + ty4 + r) * K + k0 + tx] = f2tf32(t[tx][ty4 + r]);
}

__global__ __launch_bounds__(256, 8) void round_tf32_vec(
    const float* __restrict__ in, float* __restrict__ out, size_t n4)
{
    size_t i = (size_t)blockIdx.x * blockDim.x + threadIdx.x;
    if (i < n4) {
        float4 v = ((const float4*)in)[i];
        v.x = f2tf32(v.x); v.y = f2tf32(v.y); v.z = f2tf32(v.z); v.w = f2tf32(v.w);
        ((float4*)out)[i] = v;
    }
}

__global__ void concat_bias(const float* __restrict__ bq, const float* __restrict__ bk,
                            const float* __restrict__ bv, float* __restrict__ b)
{
    int i = blockIdx.x * blockDim.x + threadIdx.x;
    if (i < QKVN)
        b[i] = (i < HIDDEN) ? bq[i]
             : (i < HIDDEN + KVSIZE) ? bk[i - HIDDEN]
             : bv[i - HIDDEN - KVSIZE];
}

// ---------------- Flash attention on mma.sync tf32 ----------------------------
// CTA: 128 query rows x 1 head, 8 warps. Reads fused qkv buffer (stride QKVN).
// K stride 68 (conflict-free S phase), V stride 72 (conflict-free P*V phase).
#define APD  68
#define VPD  72
#define ATT_Q_F  (128 * APD)
#define ATT_K_F  (64 * APD)
#define ATT_V_F  (64 * VPD)
#define ATT_SMEM ((ATT_Q_F + 2 * ATT_K_F + 2 * ATT_V_F) * 4)   // 106496 B

__global__ __launch_bounds__(256, 2) void attn_mma(
    const float* __restrict__ qkv, const float* __restrict__ mask,
    float* __restrict__ o)
{
    extern __shared__ float sm[];
    const uint32_t sbase = smem_u32(sm);
    float* Qs = sm;

    const int tid  = threadIdx.x;
    const int wid  = tid >> 5, lane = tid & 31;
    const int lr   = lane >> 2, lc = lane & 3;
    const int wm   = wid * 16;

    const int qb   = blockIdx.x;
    const int head = blockIdx.y;
    const int b    = blockIdx.z;
    const int kh   = head >> 2;
    const int r0   = qb * 128;

    const float* qbase = qkv + ((size_t)b * SEQ + r0) * QKVN + head * HDIM;
    const float* kbase = qkv + (size_t)b * SEQ * QKVN + HIDDEN + kh * HDIM;
    const float* vbase = qkv + (size_t)b * SEQ * QKVN + HIDDEN + KVSIZE + kh * HDIM;
    const float* mbase = mask + (size_t)b * SEQ;

    // ---- load Q tile (128x64) via cp.async ----
    {
        const int row = tid >> 1, c0 = (tid & 1) * 32;
        const uint32_t dst = sbase + ((uint32_t)row * APD + c0) * 4u;
        const float* src = qbase + (size_t)row * QKVN + c0;
#pragma unroll
        for (int i = 0; i < 8; i++)
            cp_async16(dst + i * 16, src + i * 4);
    }

    auto kAddr = [&](int s) { return sbase + (ATT_Q_F + (uint32_t)s * ATT_K_F) * 4u; };
    auto vAddr = [&](int s) { return sbase + (ATT_Q_F + 2u * ATT_K_F + (uint32_t)s * ATT_V_F) * 4u; };
    const int kvrow = tid >> 2;
    const int kvcb  = (tid & 3) * 16;

    auto load_kv = [&](int s, int t) {
        const uint32_t dk = kAddr(s) + ((uint32_t)kvrow * APD + kvcb) * 4u;
        const uint32_t dv = vAddr(s) + ((uint32_t)kvrow * VPD + kvcb) * 4u;
        const float* gk = kbase + (size_t)(t * 64 + kvrow) * QKVN + kvcb;
        const float* gv = vbase + (size_t)(t * 64 + kvrow) * QKVN + kvcb;
#pragma unroll
        for (int i = 0; i < 4; i++) {
            cp_async16(dk + i * 16, gk + i * 4);
            cp_async16(dv + i * 16, gv + i * 4);
        }
    };

    load_kv(0, 0);
    cp_commit();

    float Oacc[8][4];
#pragma unroll
    for (int dn = 0; dn < 8; dn++)
#pragma unroll
        for (int i = 0; i < 4; i++) Oacc[dn][i] = 0.f;
    float m1 = -1e30f, m2 = -1e30f, l1 = 0.f, l2 = 0.f;
    const float scale = 0.125f;

    const int T = SEQ / 64;
    for (int t = 0; t < T; t++) {
        const int s = t & 1;
        if (t + 1 < T) {
            load_kv(1 - s, t + 1);
            cp_commit();
            cp_wait<1>();
        } else {
            cp_wait<0>();
        }
        __syncthreads();

        const float* Ks = sm + ATT_Q_F + (size_t)s * ATT_K_F;
        const float* Vs = sm + ATT_Q_F + 2 * ATT_K_F + (size_t)s * ATT_V_F;

        // ---- S = Q @ K^T ----
        float Sacc[8][4];
#pragma unroll
        for (int nt = 0; nt < 8; nt++)
#pragma unroll
            for (int i = 0; i < 4; i++) Sacc[nt][i] = 0.f;

#pragma unroll
        for (int k8 = 0; k8 < 8; k8++) {
            const int kb = k8 * 8;
            uint32_t af[4];
            const float* qp = Qs + (size_t)(wm + lr) * APD + kb + lc;
            af[0] = __float_as_uint(qp[0]);
            af[1] = __float_as_uint(qp[8 * APD]);
            af[2] = __float_as_uint(qp[4]);
            af[3] = __float_as_uint(qp[8 * APD + 4]);
#pragma unroll
            for (int nt = 0; nt < 8; nt++) {
                const float* kp = Ks + (size_t)(nt * 8 + lr) * APD + kb + lc;
                uint32_t bf[2];
                bf[0] = __float_as_uint(kp[0]);
                bf[1] = __float_as_uint(kp[4]);
                mma_tf32(Sacc[nt], af, bf);
            }
        }

        // ---- online softmax on fragments ----
        float mx1 = -1e30f, mx2 = -1e30f;
#pragma unroll
        for (int nt = 0; nt < 8; nt++) {
            const float2 mv = *(const float2*)(mbase + t * 64 + nt * 8 + 2 * lc);
            Sacc[nt][0] = Sacc[nt][0] * scale + mv.x;
            Sacc[nt][1] = Sacc[nt][1] * scale + mv.y;
            Sacc[nt][2] = Sacc[nt][2] * scale + mv.x;
            Sacc[nt][3] = Sacc[nt][3] * scale + mv.y;
            mx1 = fmaxf(mx1, fmaxf(Sacc[nt][0], Sacc[nt][1]));
            mx2 = fmaxf(mx2, fmaxf(Sacc[nt][2], Sacc[nt][3]));
        }
        mx1 = fmaxf(mx1, __shfl_xor_sync(0xffffffffu, mx1, 1));
        mx1 = fmaxf(mx1, __shfl_xor_sync(0xffffffffu, mx1, 2));
        mx2 = fmaxf(mx2, __shfl_xor_sync(0xffffffffu, mx2, 1));
        mx2 = fmaxf(mx2, __shfl_xor_sync(0xffffffffu, mx2, 2));

        const float mn1 = fmaxf(m1, mx1), mn2 = fmaxf(m2, mx2);
        const float al1 = __expf(m1 - mn1), al2 = __expf(m2 - mn2);
        m1 = mn1; m2 = mn2;

        float sum1 = 0.f, sum2 = 0.f;
#pragma unroll
        for (int nt = 0; nt < 8; nt++) {
            Sacc[nt][0] = __expf(Sacc[nt][0] - mn1);
            Sacc[nt][1] = __expf(Sacc[nt][1] - mn1);
            Sacc[nt][2] = __expf(Sacc[nt][2] - mn2);
            Sacc[nt][3] = __expf(Sacc[nt][3] - mn2);
            sum1 += Sacc[nt][0] + Sacc[nt][1];
            sum2 += Sacc[nt][2] + Sacc[nt][3];
        }
        sum1 += __shfl_xor_sync(0xffffffffu, sum1, 1);
        sum1 += __shfl_xor_sync(0xffffffffu, sum1, 2);
        sum2 += __shfl_xor_sync(0xffffffffu, sum2, 1);
        sum2 += __shfl_xor_sync(0xffffffffu, sum2, 2);
        l1 = l1 * al1 + sum1;
        l2 = l2 * al2 + sum2;

#pragma unroll
        for (int dn = 0; dn < 8; dn++) {
            Oacc[dn][0] *= al1; Oacc[dn][1] *= al1;
            Oacc[dn][2] *= al2; Oacc[dn][3] *= al2;
        }

        // ---- O += P @ V : P frags from Sacc via quad shuffles ----
        const int src0 = (lane & 28) | (lc >> 1);
        const int src1 = src0 + 2;
        const bool odd = (lc & 1);
#pragma unroll
        for (int kk = 0; kk < 8; kk++) {
            float s0 = __shfl_sync(0xffffffffu, Sacc[kk][0], src0);
            float s1 = __shfl_sync(0xffffffffu, Sacc[kk][1], src0);
            float s2 = __shfl_sync(0xffffffffu, Sacc[kk][0], src1);
            float s3 = __shfl_sync(0xffffffffu, Sacc[kk][1], src1);
            float s4 = __shfl_sync(0xffffffffu, Sacc[kk][2], src0);
            float s5 = __shfl_sync(0xffffffffu, Sacc[kk][3], src0);
            float s6 = __shfl_sync(0xffffffffu, Sacc[kk][2], src1);
            float s7 = __shfl_sync(0xffffffffu, Sacc[kk][3], src1);
            uint32_t af[4];
            af[0] = __float_as_uint(f2tf32(odd ? s1 : s0));
            af[1] = __float_as_uint(f2tf32(odd ? s5 : s4));
            af[2] = __float_as_uint(f2tf32(odd ? s3 : s2));
            af[3] = __float_as_uint(f2tf32(odd ? s7 : s6));
#pragma unroll
            for (int dn = 0; dn < 8; dn++) {
                const float* vp = Vs + (size_t)(kk * 8 + lc) * VPD + dn * 8 + lr;
                uint32_t bf[2];
                bf[0] = __float_as_uint(vp[0]);
                bf[1] = __float_as_uint(vp[4 * VPD]);
                mma_tf32(Oacc[dn], af, bf);
            }
        }
        __syncthreads();
    }

    // ---- normalize + store ----
    const float inv1 = __frcp_rn(l1), inv2 = __frcp_rn(l2);
    const int row1 = r0 + wm + lr, row2 = row1 + 8;
    float* o1 = o + ((size_t)b * SEQ + row1) * HIDDEN + head * HDIM;
    float* o2 = o + ((size_t)b * SEQ + row2) * HIDDEN + head * HDIM;
#pragma unroll
    for (int dn = 0; dn < 8; dn++) {
        const int col = dn * 8 + 2 * lc;
        float2 v1, v2;
        v1.x = f2tf32(Oacc[dn][0] * inv1); v1.y = f2tf32(Oacc[dn][1] * inv1);
        v2.x = f2tf32(Oacc[dn][2] * inv2); v2.y = f2tf32(Oacc[dn][3] * inv2);
        *(float2*)(o1 + col) = v1;
        *(float2*)(o2 + col) = v2;
    }
}

// ---------------- host launcher -----------------------------------------------
extern "C" void kernel_launch(void* const* d_in, const int* in_sizes, int n_in,
                              void* d_out, int out_size)
{
    const float* x    = (const float*)d_in[0];
    const float* mask = (const float*)d_in[1];
    const float* Wq   = (const float*)d_in[2];
    const float* bq   = (const float*)d_in[3];
    const float* Wk   = (const float*)d_in[4];
    const float* bk   = (const float*)d_in[5];
    const float* Wv   = (const float*)d_in[6];
    const float* bv   = (const float*)d_in[7];
    const float* Wo   = (const float*)d_in[8];
    const float* bo   = (const float*)d_in[9];
    float* out = (float*)d_out;

    float *qkv, *o, *xr, *wt, *wot, *bqkv;
    cudaGetSymbolAddress((void**)&qkv,  g_qkv);
    cudaGetSymbolAddress((void**)&o,    g_o);
    cudaGetSymbolAddress((void**)&xr,   g_xr);
    cudaGetSymbolAddress((void**)&wt,   g_wt);
    cudaGetSymbolAddress((void**)&wot,  g_wot);
    cudaGetSymbolAddress((void**)&bqkv, g_bqkv);

    cudaFuncSetAttribute(gemm_tf32, cudaFuncAttributeMaxDynamicSharedMemorySize, GSMEM_BYTES);
    cudaFuncSetAttribute(attn_mma,  cudaFuncAttributeMaxDynamicSharedMemorySize, ATT_SMEM);

    // prep: round x, transpose+round weights into fused buffer, concat bias
    {
        size_t n4 = (size_t)MTOT * HIDDEN / 4;
        round_tf32_vec<<<(unsigned)((n4 + 255) / 256), 256>>>(x, xr, n4);
    }
    transpose_rnd<<<dim3(HIDDEN / 32, HIDDEN / 32), 256>>>(Wq, wt, HIDDEN, HIDDEN);
    transpose_rnd<<<dim3(KVSIZE / 32, HIDDEN / 32), 256>>>(Wk, wt + (size_t)HIDDEN * HIDDEN, HIDDEN, KVSIZE);
    transpose_rnd<<<dim3(KVSIZE / 32, HIDDEN / 32), 256>>>(Wv, wt + (size_t)(HIDDEN + KVSIZE) * HIDDEN, HIDDEN, KVSIZE);
    transpose_rnd<<<dim3(HIDDEN / 32, HIDDEN / 32), 256>>>(Wo, wot, HIDDEN, HIDDEN);
    concat_bias<<<(QKVN + 255) / 256, 256>>>(bq, bk, bv, bqkv);

    // fused QKV projection (one launch, 768 CTAs)
    gemm_tf32<<<dim3(QKVN / GBN, MTOT / GBM), 256, GSMEM_BYTES>>>(xr, wt, bqkv, qkv, MTOT, QKVN, HIDDEN, 1);

    // attention (mma.sync tf32 flash, fused-qkv input)
    attn_mma<<<dim3(SEQ / 128, NHEADS, BATCH), 256, ATT_SMEM>>>(qkv, mask, o);

    // output projection (full fp32 out)
    gemm_tf32<<<dim3(HIDDEN / GBN, MTOT / GBM), 256, GSMEM_BYTES>>>(o, wot, bo, out, MTOT, HIDDEN, HIDDEN, 0);
}

// round 8
// speedup vs baseline: 4.6678x; 1.3127x over previous
#include <cuda_runtime.h>
#include <cuda_fp16.h>
#include <cstdint>
#include <math.h>

#define HIDDEN 2048
#define KVSIZE 512
#define BATCH  2
#define SEQ    2048
#define MTOT   (BATCH*SEQ)
#define NHEADS 32
#define HDIM   64
#define QKVN   (HIDDEN + 2 * KVSIZE)    // 3072

// ---------------- scratch (device globals) ------------------------------------
__device__ __half g_qkv[(size_t)MTOT * QKVN];     // fused q|k|v (half), 25 MB
__device__ __half g_o[(size_t)MTOT * HIDDEN];     // attention out (half)
__device__ __half g_xh[(size_t)MTOT * HIDDEN];    // x in half
__device__ __half g_wt[(size_t)QKVN * HIDDEN];    // [Wq^T;Wk^T;Wv^T] half
__device__ __half g_wot[(size_t)HIDDEN * HIDDEN]; // Wo^T half
__device__ float  g_bqkv[QKVN];

// ---------------- helpers -----------------------------------------------------
__device__ __forceinline__ uint32_t smem_u32(const void* p) {
    uint32_t a;
    asm("{ .reg .u64 t; cvta.to.shared.u64 t, %1; cvt.u32.u64 %0, t; }" : "=r"(a) : "l"(p));
    return a;
}
__device__ __forceinline__ void cp_async16(uint32_t saddr, const void* g) {
    asm volatile("cp.async.cg.shared.global [%0], [%1], 16;" :: "r"(saddr), "l"(g));
}
__device__ __forceinline__ void cp_commit() { asm volatile("cp.async.commit_group;"); }
template<int N> __device__ __forceinline__ void cp_wait() {
    asm volatile("cp.async.wait_group %0;" :: "n"(N));
}
__device__ __forceinline__ void mma_f16(float* c, const uint32_t* a, const uint32_t* b) {
    asm volatile(
        "mma.sync.aligned.m16n8k16.row.col.f32.f16.f16.f32 "
        "{%0,%1,%2,%3}, {%4,%5,%6,%7}, {%8,%9}, {%0,%1,%2,%3};"
        : "+f"(c[0]), "+f"(c[1]), "+f"(c[2]), "+f"(c[3])
        : "r"(a[0]), "r"(a[1]), "r"(a[2]), "r"(a[3]), "r"(b[0]), "r"(b[1]));
}
__device__ __forceinline__ void ldm_x4(uint32_t* r, uint32_t addr) {
    asm volatile("ldmatrix.sync.aligned.m8n8.x4.shared.b16 {%0,%1,%2,%3}, [%4];"
                 : "=r"(r[0]), "=r"(r[1]), "=r"(r[2]), "=r"(r[3]) : "r"(addr));
}
__device__ __forceinline__ void ldm_x4_t(uint32_t* r, uint32_t addr) {
    asm volatile("ldmatrix.sync.aligned.m8n8.x4.trans.shared.b16 {%0,%1,%2,%3}, [%4];"
                 : "=r"(r[0]), "=r"(r[1]), "=r"(r[2]), "=r"(r[3]) : "r"(addr));
}
__device__ __forceinline__ uint32_t pack_h2(float a, float b) {
    __half2 h = __float22half2_rn(make_float2(a, b));
    return *(uint32_t*)&h;
}

// ---------------- fp16 mma GEMM: C[M,N] = A[M,K] @ Bt[N,K]^T + bias -----------
// A, Bt half, K-major. 128x128 tile, BK=64, double-buffered cp.async.
#define GBM 128
#define GBN 128
#define GBK 64
#define KPAD 72                              // halves per smem row (144 B)
#define STAGE_H (128 * KPAD)                 // halves per matrix per stage
#define GSMEM_BYTES (2 * 2 * STAGE_H * 2)    // 73728 B

__global__ __launch_bounds__(256) void gemm_f16(
    const __half* __restrict__ A, const __half* __restrict__ Bt,
    const float* __restrict__ bias, __half* __restrict__ Ch,
    float* __restrict__ Cf, int M, int N, int K)
{
    extern __shared__ __half smh[];
    const uint32_t sbase = smem_u32(smh);
    const int tid  = threadIdx.x;
    const int wid  = tid >> 5, lane = tid & 31;
    const int m0   = blockIdx.y * GBM, n0 = blockIdx.x * GBN;
    const int wm   = (wid >> 2) * 64;
    const int wn   = (wid & 3) * 32;
    const int lr   = lane >> 2;
    const int lc   = lane & 3;

    const int ldrow = tid >> 1;
    const int ldcb  = (tid & 1) * 4;
    const __half* garow = A  + (size_t)(m0 + ldrow) * K;
    const __half* gbrow = Bt + (size_t)(n0 + ldrow) * K;

    auto load_stage = [&](int s, int t) {
        const uint32_t da = sbase + (uint32_t)s * 2u * STAGE_H * 2u
                          + (uint32_t)ldrow * (KPAD * 2) + (uint32_t)ldcb * 16u;
        const uint32_t db = da + STAGE_H * 2u;
        const __half* ga = garow + t * GBK + ldcb * 8;
        const __half* gb = gbrow + t * GBK + ldcb * 8;
#pragma unroll
        for (int i = 0; i < 4; i++) {
            cp_async16(da + i * 16, ga + i * 8);
            cp_async16(db + i * 16, gb + i * 8);
        }
    };

    float acc[4][4][4];
#pragma unroll
    for (int mt = 0; mt < 4; mt++)
#pragma unroll
        for (int nt = 0; nt < 4; nt++)
#pragma unroll
            for (int i = 0; i < 4; i++) acc[mt][nt][i] = 0.f;

    const int T = K / GBK;
    load_stage(0, 0);
    cp_commit();

    const int lmrow = lane & 15, lmcol = (lane >> 4) << 3;

    for (int t = 0; t < T; t++) {
        const int s = t & 1;
        if (t + 1 < T) {
            load_stage(1 - s, t + 1);
            cp_commit();
            cp_wait<1>();
        } else {
            cp_wait<0>();
        }
        __syncthreads();

        const uint32_t sa = sbase + (uint32_t)s * 2u * STAGE_H * 2u;
        const __half* sbh = smh + (size_t)s * 2 * STAGE_H + STAGE_H;

#pragma unroll
        for (int k16 = 0; k16 < GBK / 16; k16++) {
            const int kb = k16 * 16;
            uint32_t af[4][4], bf[4][2];
#pragma unroll
            for (int mt = 0; mt < 4; mt++)
                ldm_x4(af[mt], sa + ((uint32_t)(wm + mt * 16 + lmrow) * KPAD + kb + lmcol) * 2u);
#pragma unroll
            for (int nt = 0; nt < 4; nt++) {
                const __half* bp = sbh + (size_t)(wn + nt * 8 + lr) * KPAD + kb + 2 * lc;
                bf[nt][0] = *(const uint32_t*)bp;
                bf[nt][1] = *(const uint32_t*)(bp + 8);
            }
#pragma unroll
            for (int mt = 0; mt < 4; mt++)
#pragma unroll
                for (int nt = 0; nt < 4; nt++)
                    mma_f16(acc[mt][nt], af[mt], bf[nt]);
        }
        __syncthreads();
    }

#pragma unroll
    for (int nt = 0; nt < 4; nt++) {
        const int col = n0 + wn + nt * 8 + lc * 2;
        const float2 bb = *(const float2*)(bias + col);
#pragma unroll
        for (int mt = 0; mt < 4; mt++) {
            const int row = m0 + wm + mt * 16 + lr;
            const float v00 = acc[mt][nt][0] + bb.x, v01 = acc[mt][nt][1] + bb.y;
            const float v10 = acc[mt][nt][2] + bb.x, v11 = acc[mt][nt][3] + bb.y;
            if (Ch) {
                *(uint32_t*)(Ch + (size_t)row * N + col)       = pack_h2(v00, v01);
                *(uint32_t*)(Ch + (size_t)(row + 8) * N + col) = pack_h2(v10, v11);
            } else {
                *(float2*)(Cf + (size_t)row * N + col)       = make_float2(v00, v01);
                *(float2*)(Cf + (size_t)(row + 8) * N + col) = make_float2(v10, v11);
            }
        }
    }
}

// ---------------- prep kernels ------------------------------------------------
__global__ __launch_bounds__(256, 4) void transpose_h(
    const float* __restrict__ W, __half* __restrict__ Wt, int K, int N)
{
    __shared__ float t[32][33];
    const int tx = threadIdx.x & 31, ty4 = (threadIdx.x >> 5) * 4;
    const int k0 = blockIdx.y * 32, n0 = blockIdx.x * 32;
#pragma unroll
    for (int r = 0; r < 4; r++)
        t[ty4 + r][tx] = W[(size_t)(k0 + ty4 + r) * N + n0 + tx];
    __syncthreads();
#pragma unroll
    for (int r = 0; r < 4; r++)
        Wt[(size_t)(n0 + ty4 + r) * K + k0 + tx] = __float2half_rn(t[tx][ty4 + r]);
}

__global__ __launch_bounds__(256, 8) void cvt_half_vec(
    const float* __restrict__ in, __half* __restrict__ out, size_t n4)
{
    size_t i = (size_t)blockIdx.x * blockDim.x + threadIdx.x;
    if (i < n4) {
        float4 v = ((const float4*)in)[i];
        uint2 o;
        o.x = pack_h2(v.x, v.y);
        o.y = pack_h2(v.z, v.w);
        ((uint2*)out)[i] = o;
    }
}

__global__ void concat_bias(const float* __restrict__ bq, const float* __restrict__ bk,
                            const float* __restrict__ bv, float* __restrict__ b)
{
    int i = blockIdx.x * blockDim.x + threadIdx.x;
    if (i < QKVN)
        b[i] = (i < HIDDEN) ? bq[i]
             : (i < HIDDEN + KVSIZE) ? bk[i - HIDDEN]
             : bv[i - HIDDEN - KVSIZE];
}

// ---------------- Flash attention, fp16 mma -----------------------------------
// CTA: 128 query rows x 1 head, 8 warps. K/V 64-key tiles, double-buffered.
#define HPD 72                                // halves per row (144 B)
#define ATT_Q_H  (128 * HPD)
#define ATT_KV_H (64 * HPD)
#define ATT_SMEM ((ATT_Q_H + 4 * ATT_KV_H) * 2)   // 55296 B

__global__ __launch_bounds__(256, 2) void attn_f16(
    const __half* __restrict__ qkv, const float* __restrict__ mask,
    __half* __restrict__ o)
{
    extern __shared__ __half smh[];
    const uint32_t sbase = smem_u32(smh);

    const int tid  = threadIdx.x;
    const int wid  = tid >> 5, lane = tid & 31;
    const int lr   = lane >> 2, lc = lane & 3;
    const int wm   = wid * 16;
    const int lmrow = lane & 15, lmcol = (lane >> 4) << 3;

    const int qb   = blockIdx.x;
    const int head = blockIdx.y;
    const int b    = blockIdx.z;
    const int kh   = head >> 2;
    const int r0   = qb * 128;

    const __half* qbase = qkv + ((size_t)b * SEQ + r0) * QKVN + head * HDIM;
    const __half* kbase = qkv + (size_t)b * SEQ * QKVN + HIDDEN + kh * HDIM;
    const __half* vbase = qkv + (size_t)b * SEQ * QKVN + HIDDEN + KVSIZE + kh * HDIM;
    const float*  mbase = mask + (size_t)b * SEQ;

    // ---- load Q tile (128x64 halves) ----
    {
        const int row = tid >> 1, cb = (tid & 1) * 4;
        const uint32_t dst = sbase + (uint32_t)row * (HPD * 2) + (uint32_t)cb * 16u;
        const __half* src = qbase + (size_t)row * QKVN + cb * 8;
#pragma unroll
        for (int i = 0; i < 4; i++)
            cp_async16(dst + i * 16, src + i * 8);
    }

    const uint32_t kbase_sm = sbase + ATT_Q_H * 2u;
    const uint32_t vbase_sm = kbase_sm + 2u * ATT_KV_H * 2u;
    const int kvrow = tid >> 2, kvcb = (tid & 3) * 2;

    auto load_kv = [&](int s, int t) {
        const uint32_t dk = kbase_sm + (uint32_t)s * ATT_KV_H * 2u
                          + (uint32_t)kvrow * (HPD * 2) + (uint32_t)kvcb * 16u;
        const uint32_t dv = vbase_sm + (uint32_t)s * ATT_KV_H * 2u
                          + (uint32_t)kvrow * (HPD * 2) + (uint32_t)kvcb * 16u;
        const __half* gk = kbase + (size_t)(t * 64 + kvrow) * QKVN + kvcb * 8;
        const __half* gv = vbase + (size_t)(t * 64 + kvrow) * QKVN + kvcb * 8;
#pragma unroll
        for (int i = 0; i < 2; i++) {
            cp_async16(dk + i * 16, gk + i * 8);
            cp_async16(dv + i * 16, gv + i * 8);
        }
    };

    load_kv(0, 0);
    cp_commit();

    float Oacc[8][4];
#pragma unroll
    for (int dn = 0; dn < 8; dn++)
#pragma unroll
        for (int i = 0; i < 4; i++) Oacc[dn][i] = 0.f;
    float m1 = -1e30f, m2 = -1e30f, l1 = 0.f, l2 = 0.f;
    const float scale = 0.125f;

    const int T = SEQ / 64;
    for (int t = 0; t < T; t++) {
        const int s = t & 1;
        if (t + 1 < T) {
            load_kv(1 - s, t + 1);
            cp_commit();
            cp_wait<1>();
        } else {
            cp_wait<0>();
        }
        __syncthreads();

        const __half* Ks = smh + ATT_Q_H + (size_t)s * ATT_KV_H;
        const uint32_t vs = vbase_sm + (uint32_t)s * ATT_KV_H * 2u;

        // ---- S = Q @ K^T ----
        float Sacc[8][4];
#pragma unroll
        for (int nt = 0; nt < 8; nt++)
#pragma unroll
            for (int i = 0; i < 4; i++) Sacc[nt][i] = 0.f;

#pragma unroll
        for (int k16 = 0; k16 < 4; k16++) {
            const int kb = k16 * 16;
            uint32_t af[4];
            ldm_x4(af, sbase + ((uint32_t)(wm + lmrow) * HPD + kb + lmcol) * 2u);
#pragma unroll
            for (int nt = 0; nt < 8; nt++) {
                const __half* kp = Ks + (size_t)(nt * 8 + lr) * HPD + kb + 2 * lc;
                uint32_t bf[2];
                bf[0] = *(const uint32_t*)kp;
                bf[1] = *(const uint32_t*)(kp + 8);
                mma_f16(Sacc[nt], af, bf);
            }
        }

        // ---- online softmax ----
        float mx1 = -1e30f, mx2 = -1e30f;
#pragma unroll
        for (int nt = 0; nt < 8; nt++) {
            const float2 mv = *(const float2*)(mbase + t * 64 + nt * 8 + 2 * lc);
            Sacc[nt][0] = Sacc[nt][0] * scale + mv.x;
            Sacc[nt][1] = Sacc[nt][1] * scale + mv.y;
            Sacc[nt][2] = Sacc[nt][2] * scale + mv.x;
            Sacc[nt][3] = Sacc[nt][3] * scale + mv.y;
            mx1 = fmaxf(mx1, fmaxf(Sacc[nt][0], Sacc[nt][1]));
            mx2 = fmaxf(mx2, fmaxf(Sacc[nt][2], Sacc[nt][3]));
        }
        mx1 = fmaxf(mx1, __shfl_xor_sync(0xffffffffu, mx1, 1));
        mx1 = fmaxf(mx1, __shfl_xor_sync(0xffffffffu, mx1, 2));
        mx2 = fmaxf(mx2, __shfl_xor_sync(0xffffffffu, mx2, 1));
        mx2 = fmaxf(mx2, __shfl_xor_sync(0xffffffffu, mx2, 2));

        const float mn1 = fmaxf(m1, mx1), mn2 = fmaxf(m2, mx2);
        const float al1 = __expf(m1 - mn1), al2 = __expf(m2 - mn2);
        m1 = mn1; m2 = mn2;

        float sum1 = 0.f, sum2 = 0.f;
#pragma unroll
        for (int nt = 0; nt < 8; nt++) {
            Sacc[nt][0] = __expf(Sacc[nt][0] - mn1);
            Sacc[nt][1] = __expf(Sacc[nt][1] - mn1);
            Sacc[nt][2] = __expf(Sacc[nt][2] - mn2);
            Sacc[nt][3] = __expf(Sacc[nt][3] - mn2);
            sum1 += Sacc[nt][0] + Sacc[nt][1];
            sum2 += Sacc[nt][2] + Sacc[nt][3];
        }
        sum1 += __shfl_xor_sync(0xffffffffu, sum1, 1);
        sum1 += __shfl_xor_sync(0xffffffffu, sum1, 2);
        sum2 += __shfl_xor_sync(0xffffffffu, sum2, 1);
        sum2 += __shfl_xor_sync(0xffffffffu, sum2, 2);
        l1 = l1 * al1 + sum1;
        l2 = l2 * al2 + sum2;

#pragma unroll
        for (int dn = 0; dn < 8; dn++) {
            Oacc[dn][0] *= al1; Oacc[dn][1] *= al1;
            Oacc[dn][2] *= al2; Oacc[dn][3] *= al2;
        }

        // ---- O += P @ V : P-frags are direct half2 packs of Sacc ----
#pragma unroll
        for (int j = 0; j < 4; j++) {
            uint32_t af[4];
            af[0] = pack_h2(Sacc[2 * j][0],     Sacc[2 * j][1]);
            af[1] = pack_h2(Sacc[2 * j][2],     Sacc[2 * j][3]);
            af[2] = pack_h2(Sacc[2 * j + 1][0], Sacc[2 * j + 1][1]);
            af[3] = pack_h2(Sacc[2 * j + 1][2], Sacc[2 * j + 1][3]);
#pragma unroll
            for (int dnp = 0; dnp < 4; dnp++) {
                uint32_t bf[4];
                ldm_x4_t(bf, vs + ((uint32_t)(16 * j + lmrow) * HPD + dnp * 16 + lmcol) * 2u);
                mma_f16(Oacc[2 * dnp],     af, bf);
                mma_f16(Oacc[2 * dnp + 1], af, bf + 2);
            }
        }
        __syncthreads();
    }

    // ---- normalize + store (half) ----
    const float inv1 = __frcp_rn(l1), inv2 = __frcp_rn(l2);
    const int row1 = r0 + wm + lr, row2 = row1 + 8;
    __half* o1 = o + ((size_t)b * SEQ + row1) * HIDDEN + head * HDIM;
    __half* o2 = o + ((size_t)b * SEQ + row2) * HIDDEN + head * HDIM;
#pragma unroll
    for (int dn = 0; dn < 8; dn++) {
        const int col = dn * 8 + 2 * lc;
        *(uint32_t*)(o1 + col) = pack_h2(Oacc[dn][0] * inv1, Oacc[dn][1] * inv1);
        *(uint32_t*)(o2 + col) = pack_h2(Oacc[dn][2] * inv2, Oacc[dn][3] * inv2);
    }
}

// ---------------- host launcher -----------------------------------------------
extern "C" void kernel_launch(void* const* d_in, const int* in_sizes, int n_in,
                              void* d_out, int out_size)
{
    const float* x    = (const float*)d_in[0];
    const float* mask = (const float*)d_in[1];
    const float* Wq   = (const float*)d_in[2];
    const float* bq   = (const float*)d_in[3];
    const float* Wk   = (const float*)d_in[4];
    const float* bk   = (const float*)d_in[5];
    const float* Wv   = (const float*)d_in[6];
    const float* bv   = (const float*)d_in[7];
    const float* Wo   = (const float*)d_in[8];
    const float* bo   = (const float*)d_in[9];
    float* out = (float*)d_out;

    __half *qkv, *o, *xh, *wt, *wot;
    float *bqkv;
    cudaGetSymbolAddress((void**)&qkv,  g_qkv);
    cudaGetSymbolAddress((void**)&o,    g_o);
    cudaGetSymbolAddress((void**)&xh,   g_xh);
    cudaGetSymbolAddress((void**)&wt,   g_wt);
    cudaGetSymbolAddress((void**)&wot,  g_wot);
    cudaGetSymbolAddress((void**)&bqkv, g_bqkv);

    cudaFuncSetAttribute(gemm_f16, cudaFuncAttributeMaxDynamicSharedMemorySize, GSMEM_BYTES);
    cudaFuncSetAttribute(attn_f16, cudaFuncAttributeMaxDynamicSharedMemorySize, ATT_SMEM);

    // prep: x -> half, weights -> transposed half, fused bias
    {
        size_t n4 = (size_t)MTOT * HIDDEN / 4;
        cvt_half_vec<<<(unsigned)((n4 + 255) / 256), 256>>>(x, xh, n4);
    }
    transpose_h<<<dim3(HIDDEN / 32, HIDDEN / 32), 256>>>(Wq, wt, HIDDEN, HIDDEN);
    transpose_h<<<dim3(KVSIZE / 32, HIDDEN / 32), 256>>>(Wk, wt + (size_t)HIDDEN * HIDDEN, HIDDEN, KVSIZE);
    transpose_h<<<dim3(KVSIZE / 32, HIDDEN / 32), 256>>>(Wv, wt + (size_t)(HIDDEN + KVSIZE) * HIDDEN, HIDDEN, KVSIZE);
    transpose_h<<<dim3(HIDDEN / 32, HIDDEN / 32), 256>>>(Wo, wot, HIDDEN, HIDDEN);
    concat_bias<<<(QKVN + 255) / 256, 256>>>(bq, bk, bv, bqkv);

    // fused QKV projection -> half qkv
    gemm_f16<<<dim3(QKVN / GBN, MTOT / GBM), 256, GSMEM_BYTES>>>(
        xh, wt, bqkv, qkv, nullptr, MTOT, QKVN, HIDDEN);

    // attention (fp16 mma flash)
    attn_f16<<<dim3(SEQ / 128, NHEADS, BATCH), 256, ATT_SMEM>>>(qkv, mask, o);

    // output projection -> fp32 out
    gemm_f16<<<dim3(HIDDEN / GBN, MTOT / GBM), 256, GSMEM_BYTES>>>(
        o, wot, bo, nullptr, out, MTOT, HIDDEN, HIDDEN);
}

// round 13
// speedup vs baseline: 7.7792x; 1.6666x over previous
#include <cuda_runtime.h>
#include <cuda_fp16.h>
#include <cstdint>
#include <math.h>

#define HIDDEN 2048
#define KVSIZE 512
#define BATCH  2
#define SEQ    2048
#define MTOT   (BATCH*SEQ)
#define NHEADS 32
#define HDIM   64
#define QKVN   (HIDDEN + 2 * KVSIZE)    // 3072
#define LOG2E  1.4426950408889634f

// ---------------- scratch (device globals) ------------------------------------
__device__ __half g_qkv[(size_t)MTOT * QKVN];
__device__ __half g_o[(size_t)MTOT * HIDDEN];
__device__ __half g_xh[(size_t)MTOT * HIDDEN];
__device__ __half g_wt[(size_t)QKVN * HIDDEN];
__device__ __half g_wot[(size_t)HIDDEN * HIDDEN];
__device__ float  g_bqkv[QKVN];

// ---------------- helpers -----------------------------------------------------
__device__ __forceinline__ uint32_t smem_u32(const void* p) {
    uint32_t a;
    asm("{ .reg .u64 t; cvta.to.shared.u64 t, %1; cvt.u32.u64 %0, t; }" : "=r"(a) : "l"(p));
    return a;
}
__device__ __forceinline__ void cp_async16(uint32_t saddr, const void* g) {
    asm volatile("cp.async.cg.shared.global [%0], [%1], 16;" :: "r"(saddr), "l"(g));
}
__device__ __forceinline__ void cp_commit() { asm volatile("cp.async.commit_group;"); }
template<int N> __device__ __forceinline__ void cp_wait() {
    asm volatile("cp.async.wait_group %0;" :: "n"(N));
}
__device__ __forceinline__ void mma_f16(float* c, const uint32_t* a, const uint32_t* b) {
    asm volatile(
        "mma.sync.aligned.m16n8k16.row.col.f32.f16.f16.f32 "
        "{%0,%1,%2,%3}, {%4,%5,%6,%7}, {%8,%9}, {%0,%1,%2,%3};"
        : "+f"(c[0]), "+f"(c[1]), "+f"(c[2]), "+f"(c[3])
        : "r"(a[0]), "r"(a[1]), "r"(a[2]), "r"(a[3]), "r"(b[0]), "r"(b[1]));
}
__device__ __forceinline__ void ldm_x4(uint32_t* r, uint32_t addr) {
    asm volatile("ldmatrix.sync.aligned.m8n8.x4.shared.b16 {%0,%1,%2,%3}, [%4];"
                 : "=r"(r[0]), "=r"(r[1]), "=r"(r[2]), "=r"(r[3]) : "r"(addr));
}
__device__ __forceinline__ void ldm_x4_t(uint32_t* r, uint32_t addr) {
    asm volatile("ldmatrix.sync.aligned.m8n8.x4.trans.shared.b16 {%0,%1,%2,%3}, [%4];"
                 : "=r"(r[0]), "=r"(r[1]), "=r"(r[2]), "=r"(r[3]) : "r"(addr));
}
__device__ __forceinline__ uint32_t pack_h2(float a, float b) {
    __half2 h = __float22half2_rn(make_float2(a, b));
    return *(uint32_t*)&h;
}
__device__ __forceinline__ uint32_t ex2_h2(uint32_t x) {
    uint32_t d;
    asm("ex2.approx.f16x2 %0, %1;" : "=r"(d) : "r"(x));
    return d;
}

// ---------------- fp16 mma GEMM: C[M,N] = A[M,K] @ Bt[N,K]^T + bias -----------
#define GBM 128
#define GBN 128
#define GBK 64
#define KPAD 72
#define STAGE_H (128 * KPAD)
#define GSMEM_BYTES (2 * 2 * STAGE_H * 2)

__global__ __launch_bounds__(256) void gemm_f16(
    const __half* __restrict__ A, const __half* __restrict__ Bt,
    const float* __restrict__ bias, __half* __restrict__ Ch,
    float* __restrict__ Cf, int M, int N, int K)
{
    extern __shared__ __half smh[];
    const uint32_t sbase = smem_u32(smh);
    const int tid  = threadIdx.x;
    const int wid  = tid >> 5, lane = tid & 31;
    const int m0   = blockIdx.y * GBM, n0 = blockIdx.x * GBN;
    const int wm   = (wid >> 2) * 64;
    const int wn   = (wid & 3) * 32;
    const int lr   = lane >> 2;
    const int lc   = lane & 3;
    const int lmrow = lane & 15, lmcol = (lane >> 4) << 3;
    const int blrow = ((lane >> 4) << 3) + (lane & 7);   // 0..15
    const int blcol = ((lane >> 3) & 1) << 3;            // 0 or 8

    const int ldrow = tid >> 1;
    const int ldcb  = (tid & 1) * 4;
    const __half* garow = A  + (size_t)(m0 + ldrow) * K;
    const __half* gbrow = Bt + (size_t)(n0 + ldrow) * K;

    auto load_stage = [&](int s, int t) {
        const uint32_t da = sbase + (uint32_t)s * 2u * STAGE_H * 2u
                          + (uint32_t)ldrow * (KPAD * 2) + (uint32_t)ldcb * 16u;
        const uint32_t db = da + STAGE_H * 2u;
        const __half* ga = garow + t * GBK + ldcb * 8;
        const __half* gb = gbrow + t * GBK + ldcb * 8;
#pragma unroll
        for (int i = 0; i < 4; i++) {
            cp_async16(da + i * 16, ga + i * 8);
            cp_async16(db + i * 16, gb + i * 8);
        }
    };

    float acc[4][4][4];
#pragma unroll
    for (int mt = 0; mt < 4; mt++)
#pragma unroll
        for (int nt = 0; nt < 4; nt++)
#pragma unroll
            for (int i = 0; i < 4; i++) acc[mt][nt][i] = 0.f;

    const int T = K / GBK;
    load_stage(0, 0);
    cp_commit();

    for (int t = 0; t < T; t++) {
        const int s = t & 1;
        if (t + 1 < T) {
            load_stage(1 - s, t + 1);
            cp_commit();
            cp_wait<1>();
        } else {
            cp_wait<0>();
        }
        __syncthreads();

        const uint32_t sa = sbase + (uint32_t)s * 2u * STAGE_H * 2u;
        const uint32_t sb = sa + STAGE_H * 2u;

#pragma unroll
        for (int k16 = 0; k16 < GBK / 16; k16++) {
            const int kb = k16 * 16;
            uint32_t af[4][4], bf[4][2];
#pragma unroll
            for (int mt = 0; mt < 4; mt++)
                ldm_x4(af[mt], sa + ((uint32_t)(wm + mt * 16 + lmrow) * KPAD + kb + lmcol) * 2u);
#pragma unroll
            for (int ntp = 0; ntp < 2; ntp++) {
                uint32_t r[4];
                ldm_x4(r, sb + ((uint32_t)(wn + ntp * 16 + blrow) * KPAD + kb + blcol) * 2u);
                bf[2 * ntp][0] = r[0]; bf[2 * ntp][1] = r[1];
                bf[2 * ntp + 1][0] = r[2]; bf[2 * ntp + 1][1] = r[3];
            }
#pragma unroll
            for (int mt = 0; mt < 4; mt++)
#pragma unroll
                for (int nt = 0; nt < 4; nt++)
                    mma_f16(acc[mt][nt], af[mt], bf[nt]);
        }
        __syncthreads();
    }

#pragma unroll
    for (int nt = 0; nt < 4; nt++) {
        const int col = n0 + wn + nt * 8 + lc * 2;
        const float2 bb = *(const float2*)(bias + col);
#pragma unroll
        for (int mt = 0; mt < 4; mt++) {
            const int row = m0 + wm + mt * 16 + lr;
            const float v00 = acc[mt][nt][0] + bb.x, v01 = acc[mt][nt][1] + bb.y;
            const float v10 = acc[mt][nt][2] + bb.x, v11 = acc[mt][nt][3] + bb.y;
            if (Ch) {
                *(uint32_t*)(Ch + (size_t)row * N + col)       = pack_h2(v00, v01);
                *(uint32_t*)(Ch + (size_t)(row + 8) * N + col) = pack_h2(v10, v11);
            } else {
                *(float2*)(Cf + (size_t)row * N + col)       = make_float2(v00, v01);
                *(float2*)(Cf + (size_t)(row + 8) * N + col) = make_float2(v10, v11);
            }
        }
    }
}

// ---------------- prep kernels ------------------------------------------------
__global__ __launch_bounds__(256, 4) void transpose_h(
    const float* __restrict__ W, __half* __restrict__ Wt, int K, int N)
{
    __shared__ float t[32][33];
    const int tx = threadIdx.x & 31, ty4 = (threadIdx.x >> 5) * 4;
    const int k0 = blockIdx.y * 32, n0 = blockIdx.x * 32;
#pragma unroll
    for (int r = 0; r < 4; r++)
        t[ty4 + r][tx] = W[(size_t)(k0 + ty4 + r) * N + n0 + tx];
    __syncthreads();
#pragma unroll
    for (int r = 0; r < 4; r++)
        Wt[(size_t)(n0 + ty4 + r) * K + k0 + tx] = __float2half_rn(t[tx][ty4 + r]);
}

__global__ __launch_bounds__(256, 8) void cvt_half_vec(
    const float* __restrict__ in, __half* __restrict__ out, size_t n4)
{
    size_t i = (size_t)blockIdx.x * blockDim.x + threadIdx.x;
    if (i < n4) {
        float4 v = ((const float4*)in)[i];
        uint2 o;
        o.x = pack_h2(v.x, v.y);
        o.y = pack_h2(v.z, v.w);
        ((uint2*)out)[i] = o;
    }
}

__global__ void concat_bias(const float* __restrict__ bq, const float* __restrict__ bk,
                            const float* __restrict__ bv, float* __restrict__ b)
{
    int i = blockIdx.x * blockDim.x + threadIdx.x;
    if (i < QKVN)
        b[i] = (i < HIDDEN) ? bq[i]
             : (i < HIDDEN + KVSIZE) ? bk[i - HIDDEN]
             : bv[i - HIDDEN - KVSIZE];
}

// ---------------- Flash attention, fp16 mma, base-2 softmax -------------------
#define HPD 72
#define ATT_Q_H  (128 * HPD)
#define ATT_KV_H (64 * HPD)
#define ATT_SMEM ((ATT_Q_H + 4 * ATT_KV_H) * 2)   // 55296 B

__global__ __launch_bounds__(256, 2) void attn_f16(
    const __half* __restrict__ qkv, const float* __restrict__ mask,
    __half* __restrict__ o)
{
    extern __shared__ __half smh[];
    const uint32_t sbase = smem_u32(smh);

    const int tid  = threadIdx.x;
    const int wid  = tid >> 5, lane = tid & 31;
    const int lr   = lane >> 2, lc = lane & 3;
    const int wm   = wid * 16;
    const int lmrow = lane & 15, lmcol = (lane >> 4) << 3;

    const int qb   = blockIdx.x;
    const int head = blockIdx.y;
    const int b    = blockIdx.z;
    const int kh   = head >> 2;
    const int r0   = qb * 128;

    const __half* qbase = qkv + ((size_t)b * SEQ + r0) * QKVN + head * HDIM;
    const __half* kbase = qkv + (size_t)b * SEQ * QKVN + HIDDEN + kh * HDIM;
    const __half* vbase = qkv + (size_t)b * SEQ * QKVN + HIDDEN + KVSIZE + kh * HDIM;
    const float*  mbase = mask + (size_t)b * SEQ;

    // ---- load Q tile ----
    {
        const int row = tid >> 1, cb = (tid & 1) * 4;
        const uint32_t dst = sbase + (uint32_t)row * (HPD * 2) + (uint32_t)cb * 16u;
        const __half* src = qbase + (size_t)row * QKVN + cb * 8;
#pragma unroll
        for (int i = 0; i < 4; i++)
            cp_async16(dst + i * 16, src + i * 8);
    }

    const uint32_t kbase_sm = sbase + ATT_Q_H * 2u;
    const uint32_t vbase_sm = kbase_sm + 2u * ATT_KV_H * 2u;
    const int kvrow = tid >> 2, kvcb = (tid & 3) * 2;

    auto load_kv = [&](int s, int t) {
        const uint32_t dk = kbase_sm + (uint32_t)s * ATT_KV_H * 2u
                          + (uint32_t)kvrow * (HPD * 2) + (uint32_t)kvcb * 16u;
        const uint32_t dv = vbase_sm + (uint32_t)s * ATT_KV_H * 2u
                          + (uint32_t)kvrow * (HPD * 2) + (uint32_t)kvcb * 16u;
        const __half* gk = kbase + (size_t)(t * 64 + kvrow) * QKVN + kvcb * 8;
        const __half* gv = vbase + (size_t)(t * 64 + kvrow) * QKVN + kvcb * 8;
#pragma unroll
        for (int i = 0; i < 2; i++) {
            cp_async16(dk + i * 16, gk + i * 8);
            cp_async16(dv + i * 16, gv + i * 8);
        }
    };

    load_kv(0, 0);
    cp_commit();

    float Oacc[8][4], Lacc[4];
#pragma unroll
    for (int dn = 0; dn < 8; dn++)
#pragma unroll
        for (int i = 0; i < 4; i++) Oacc[dn][i] = 0.f;
#pragma unroll
    for (int i = 0; i < 4; i++) Lacc[i] = 0.f;
    float m1 = -1e30f, m2 = -1e30f;
    const float SC2 = 0.125f * LOG2E;     // scale * log2(e)

    // constant B-fragment of the all-ones column (n==0 lanes only)
    const uint32_t bone = (lr == 0) ? 0x3C003C00u : 0u;
    const uint32_t bcon[2] = { bone, bone };

    const int T = SEQ / 64;
    for (int t = 0; t < T; t++) {
        const int s = t & 1;
        if (t + 1 < T) {
            load_kv(1 - s, t + 1);
            cp_commit();
            cp_wait<1>();
        } else {
            cp_wait<0>();
        }
        __syncthreads();

        const __half* Ks = smh + ATT_Q_H + (size_t)s * ATT_KV_H;
        const uint32_t vs = vbase_sm + (uint32_t)s * ATT_KV_H * 2u;

        // ---- S = Q @ K^T ----
        float Sacc[8][4];
#pragma unroll
        for (int nt = 0; nt < 8; nt++)
#pragma unroll
            for (int i = 0; i < 4; i++) Sacc[nt][i] = 0.f;

#pragma unroll
        for (int k16 = 0; k16 < 4; k16++) {
            const int kb = k16 * 16;
            uint32_t af[4];
            ldm_x4(af, sbase + ((uint32_t)(wm + lmrow) * HPD + kb + lmcol) * 2u);
#pragma unroll
            for (int nt = 0; nt < 8; nt++) {
                const __half* kp = Ks + (size_t)(nt * 8 + lr) * HPD + kb + 2 * lc;
                uint32_t bf[2];
                bf[0] = *(const uint32_t*)kp;
                bf[1] = *(const uint32_t*)(kp + 8);
                mma_f16(Sacc[nt], af, bf);
            }
        }

        // ---- base-2 softmax: s2 = S*scale*log2e + mask*log2e ----
        float mx1 = -1e30f, mx2 = -1e30f;
#pragma unroll
        for (int nt = 0; nt < 8; nt++) {
            const float2 mv = *(const float2*)(mbase + t * 64 + nt * 8 + 2 * lc);
            const float mlx = mv.x * LOG2E, mly = mv.y * LOG2E;
            Sacc[nt][0] = fmaf(Sacc[nt][0], SC2, mlx);
            Sacc[nt][1] = fmaf(Sacc[nt][1], SC2, mly);
            Sacc[nt][2] = fmaf(Sacc[nt][2], SC2, mlx);
            Sacc[nt][3] = fmaf(Sacc[nt][3], SC2, mly);
            mx1 = fmaxf(mx1, fmaxf(Sacc[nt][0], Sacc[nt][1]));
            mx2 = fmaxf(mx2, fmaxf(Sacc[nt][2], Sacc[nt][3]));
        }
        mx1 = fmaxf(mx1, __shfl_xor_sync(0xffffffffu, mx1, 1));
        mx1 = fmaxf(mx1, __shfl_xor_sync(0xffffffffu, mx1, 2));
        mx2 = fmaxf(mx2, __shfl_xor_sync(0xffffffffu, mx2, 1));
        mx2 = fmaxf(mx2, __shfl_xor_sync(0xffffffffu, mx2, 2));

        const float mn1 = fmaxf(m1, mx1), mn2 = fmaxf(m2, mx2);
        const float al1 = exp2f(m1 - mn1), al2 = exp2f(m2 - mn2);
        m1 = mn1; m2 = mn2;

        // P fragments directly in half2 via f16x2 exp2
        uint32_t P2[8][2];
#pragma unroll
        for (int nt = 0; nt < 8; nt++) {
            P2[nt][0] = ex2_h2(pack_h2(Sacc[nt][0] - mn1, Sacc[nt][1] - mn1));
            P2[nt][1] = ex2_h2(pack_h2(Sacc[nt][2] - mn2, Sacc[nt][3] - mn2));
        }

        // rescale running accumulators (l rides along as extra column)
#pragma unroll
        for (int dn = 0; dn < 8; dn++) {
            Oacc[dn][0] *= al1; Oacc[dn][1] *= al1;
            Oacc[dn][2] *= al2; Oacc[dn][3] *= al2;
        }
        Lacc[0] *= al1; Lacc[1] *= al1;
        Lacc[2] *= al2; Lacc[3] *= al2;

        // ---- O += P @ V,  L += P @ ones ----
#pragma unroll
        for (int j = 0; j < 4; j++) {
            uint32_t af[4];
            af[0] = P2[2 * j][0];
            af[1] = P2[2 * j][1];
            af[2] = P2[2 * j + 1][0];
            af[3] = P2[2 * j + 1][1];
#pragma unroll
            for (int dnp = 0; dnp < 4; dnp++) {
                uint32_t bf[4];
                ldm_x4_t(bf, vs + ((uint32_t)(16 * j + lmrow) * HPD + dnp * 16 + lmcol) * 2u);
                mma_f16(Oacc[2 * dnp],     af, bf);
                mma_f16(Oacc[2 * dnp + 1], af, bf + 2);
            }
            mma_f16(Lacc, af, bcon);
        }
        __syncthreads();
    }

    // ---- extract l (col 0 lanes), normalize + store ----
    const float l1 = __shfl_sync(0xffffffffu, Lacc[0], lane & 28);
    const float l2 = __shfl_sync(0xffffffffu, Lacc[2], lane & 28);
    const float inv1 = __frcp_rn(l1), inv2 = __frcp_rn(l2);
    const int row1 = r0 + wm + lr, row2 = row1 + 8;
    __half* o1 = o + ((size_t)b * SEQ + row1) * HIDDEN + head * HDIM;
    __half* o2 = o + ((size_t)b * SEQ + row2) * HIDDEN + head * HDIM;
#pragma unroll
    for (int dn = 0; dn < 8; dn++) {
        const int col = dn * 8 + 2 * lc;
        *(uint32_t*)(o1 + col) = pack_h2(Oacc[dn][0] * inv1, Oacc[dn][1] * inv1);
        *(uint32_t*)(o2 + col) = pack_h2(Oacc[dn][2] * inv2, Oacc[dn][3] * inv2);
    }
}

// ---------------- host launcher -----------------------------------------------
extern "C" void kernel_launch(void* const* d_in, const int* in_sizes, int n_in,
                              void* d_out, int out_size)
{
    const float* x    = (const float*)d_in[0];
    const float* mask = (const float*)d_in[1];
    const float* Wq   = (const float*)d_in[2];
    const float* bq   = (const float*)d_in[3];
    const float* Wk   = (const float*)d_in[4];
    const float* bk   = (const float*)d_in[5];
    const float* Wv   = (const float*)d_in[6];
    const float* bv   = (const float*)d_in[7];
    const float* Wo   = (const float*)d_in[8];
    const float* bo   = (const float*)d_in[9];
    float* out = (float*)d_out;

    __half *qkv, *o, *xh, *wt, *wot;
    float *bqkv;
    cudaGetSymbolAddress((void**)&qkv,  g_qkv);
    cudaGetSymbolAddress((void**)&o,    g_o);
    cudaGetSymbolAddress((void**)&xh,   g_xh);
    cudaGetSymbolAddress((void**)&wt,   g_wt);
    cudaGetSymbolAddress((void**)&wot,  g_wot);
    cudaGetSymbolAddress((void**)&bqkv, g_bqkv);

    cudaFuncSetAttribute(gemm_f16, cudaFuncAttributeMaxDynamicSharedMemorySize, GSMEM_BYTES);
    cudaFuncSetAttribute(attn_f16, cudaFuncAttributeMaxDynamicSharedMemorySize, ATT_SMEM);

    {
        size_t n4 = (size_t)MTOT * HIDDEN / 4;
        cvt_half_vec<<<(unsigned)((n4 + 255) / 256), 256>>>(x, xh, n4);
    }
    transpose_h<<<dim3(HIDDEN / 32, HIDDEN / 32), 256>>>(Wq, wt, HIDDEN, HIDDEN);
    transpose_h<<<dim3(KVSIZE / 32, HIDDEN / 32), 256>>>(Wk, wt + (size_t)HIDDEN * HIDDEN, HIDDEN, KVSIZE);
    transpose_h<<<dim3(KVSIZE / 32, HIDDEN / 32), 256>>>(Wv, wt + (size_t)(HIDDEN + KVSIZE) * HIDDEN, HIDDEN, KVSIZE);
    transpose_h<<<dim3(HIDDEN / 32, HIDDEN / 32), 256>>>(Wo, wot, HIDDEN, HIDDEN);
    concat_bias<<<(QKVN + 255) / 256, 256>>>(bq, bk, bv, bqkv);

    gemm_f16<<<dim3(QKVN / GBN, MTOT / GBM), 256, GSMEM_BYTES>>>(
        xh, wt, bqkv, qkv, nullptr, MTOT, QKVN, HIDDEN);

    attn_f16<<<dim3(SEQ / 128, NHEADS, BATCH), 256, ATT_SMEM>>>(qkv, mask, o);

    gemm_f16<<<dim3(HIDDEN / GBN, MTOT / GBM), 256, GSMEM_BYTES>>>(
        o, wot, bo, nullptr, out, MTOT, HIDDEN, HIDDEN);
}